// round 15
// baseline (speedup 1.0000x reference)
#include <cuda_runtime.h>
#include <cuda_bf16.h>
#include <cuda_fp16.h>
#include <math.h>
#include <stdint.h>

// Problem constants (MiniGPT: B=4, T=1024, D=768, H=12, L=4, V=32000, HD=64)
#define BB 4
#define TT 1024
#define DD 768
#define HH 12
#define LL 4
#define VV 32000
#define HD 64
#define D4 (4*DD)
#define D3 (3*DD)
#define PERSIST 444   // 148 SMs x 3 CTAs/SM

// ---------------------------------------------------------------------------
// Scratch (device globals). bf16 "planes" are (hi, lo) split pairs.
// ---------------------------------------------------------------------------
__device__ float g_x[BB*TT*DD];

#define PLANE(name, n) \
  __device__ __align__(256) __nv_bfloat16 name##_hi[n]; \
  __device__ __align__(256) __nv_bfloat16 name##_lo[n];

PLANE(g_h,  BB*TT*DD)
PLANE(g_q,  BB*TT*DD)
PLANE(g_k,  BB*TT*DD)
PLANE(g_vT, BB*TT*DD)                 // [b][d][t] transposed V
PLANE(g_o,  BB*TT*DD)
PLANE(g_m,  (size_t)BB*TT*D4)         // MLP hidden
// transposed weights [N,K]; QKV concatenated: [L][3*DD][DD]
PLANE(g_wqkvT, (size_t)LL*D3*DD)
PLANE(g_woT, LL*DD*DD)
PLANE(g_w1T, (size_t)LL*D4*DD)
PLANE(g_w2T, (size_t)LL*DD*D4)
// LM head: single-plane fp16 path (error budget measured R8/R10: ~2e-4/side)
__device__ __align__(256) __half g_wlm16[(size_t)VV*DD];
__device__ __align__(256) __half g_h16[BB*TT*DD];

// ---------------------------------------------------------------------------
// Helpers
// ---------------------------------------------------------------------------
__device__ __forceinline__ void split1(float x, __nv_bfloat16 &h, __nv_bfloat16 &l) {
    h = __float2bfloat16_rn(x);
    l = __float2bfloat16_rn(x - __bfloat162float(h));
}
__device__ __forceinline__ void split2pack(float x, float y, uint32_t &hi, uint32_t &lo) {
    __nv_bfloat16 xh, xl, yh, yl;
    split1(x, xh, xl); split1(y, yh, yl);
    hi = (uint32_t)__bfloat16_as_ushort(xh) | ((uint32_t)__bfloat16_as_ushort(yh) << 16);
    lo = (uint32_t)__bfloat16_as_ushort(xl) | ((uint32_t)__bfloat16_as_ushort(yl) << 16);
}
__device__ __forceinline__ void ldsm4(uint32_t &r0, uint32_t &r1, uint32_t &r2, uint32_t &r3, uint32_t a) {
    asm volatile("ldmatrix.sync.aligned.m8n8.x4.shared.b16 {%0,%1,%2,%3}, [%4];\n"
                 : "=r"(r0), "=r"(r1), "=r"(r2), "=r"(r3) : "r"(a));
}
__device__ __forceinline__ void mma16816(float* d, const uint32_t* a, uint32_t b0, uint32_t b1) {
    asm volatile("mma.sync.aligned.m16n8k16.row.col.f32.bf16.bf16.f32 "
                 "{%0,%1,%2,%3},{%4,%5,%6,%7},{%8,%9},{%0,%1,%2,%3};\n"
                 : "+f"(d[0]), "+f"(d[1]), "+f"(d[2]), "+f"(d[3])
                 : "r"(a[0]), "r"(a[1]), "r"(a[2]), "r"(a[3]), "r"(b0), "r"(b1));
}
__device__ __forceinline__ void mma16816h(float* d, const uint32_t* a, uint32_t b0, uint32_t b1) {
    asm volatile("mma.sync.aligned.m16n8k16.row.col.f32.f16.f16.f32 "
                 "{%0,%1,%2,%3},{%4,%5,%6,%7},{%8,%9},{%0,%1,%2,%3};\n"
                 : "+f"(d[0]), "+f"(d[1]), "+f"(d[2]), "+f"(d[3])
                 : "r"(a[0]), "r"(a[1]), "r"(a[2]), "r"(a[3]), "r"(b0), "r"(b1));
}
__device__ __forceinline__ void cpa16(uint32_t dst, const void* src) {
    asm volatile("cp.async.cg.shared.global [%0], [%1], 16;\n" :: "r"(dst), "l"(src));
}
__device__ __forceinline__ void cp_commit() { asm volatile("cp.async.commit_group;\n"); }
template<int N> __device__ __forceinline__ void cp_waitg() {
    asm volatile("cp.async.wait_group %0;\n" :: "n"(N));
}
__device__ __forceinline__ void cp_wait1() { asm volatile("cp.async.wait_group 1;\n"); }
__device__ __forceinline__ void cp_wait0() { asm volatile("cp.async.wait_group 0;\n"); }
// byte offset of 16B chunk c (0..3) in a 64B row, XOR swizzle for ldmatrix
__device__ __forceinline__ uint32_t swzc(int row, int c) {
    return (uint32_t)(row * 64 + ((c ^ ((row >> 1) & 3)) << 4));
}

// ---------------------------------------------------------------------------
// Weight prep: transpose [K,N] fp32 -> [N,K] bf16 hi/lo planes.
// ---------------------------------------------------------------------------
__global__ void transpose_split(const float* __restrict__ in,
                                __nv_bfloat16* __restrict__ oh,
                                __nv_bfloat16* __restrict__ ol,
                                int K, int N, long long ostride) {
    in += (size_t)blockIdx.z * K * N;
    oh += (size_t)blockIdx.z * ostride;
    ol += (size_t)blockIdx.z * ostride;
    __shared__ float tile[32][33];
    int n0 = blockIdx.x * 32, k0 = blockIdx.y * 32;
    int tx = threadIdx.x, ty = threadIdx.y;
    #pragma unroll
    for (int i = 0; i < 4; i++)
        tile[ty + i*8][tx] = in[(size_t)(k0 + ty + i*8) * N + n0 + tx];
    __syncthreads();
    #pragma unroll
    for (int i = 0; i < 4; i++) {
        float v = tile[tx][ty + i*8];
        __nv_bfloat16 h, l;
        split1(v, h, l);
        size_t off = (size_t)(n0 + ty + i*8) * K + k0 + tx;
        oh[off] = h;
        ol[off] = l;
    }
}

// fp16 single-plane variant (LM head weights)
__global__ void transpose_f16(const float* __restrict__ in,
                              __half* __restrict__ oh,
                              int K, int N) {
    __shared__ float tile[32][33];
    int n0 = blockIdx.x * 32, k0 = blockIdx.y * 32;
    int tx = threadIdx.x, ty = threadIdx.y;
    #pragma unroll
    for (int i = 0; i < 4; i++)
        tile[ty + i*8][tx] = in[(size_t)(k0 + ty + i*8) * N + n0 + tx];
    __syncthreads();
    #pragma unroll
    for (int i = 0; i < 4; i++) {
        float v = tile[tx][ty + i*8];
        size_t off = (size_t)(n0 + ty + i*8) * K + k0 + tx;
        oh[off] = __float2half_rn(v);
    }
}

// ---------------------------------------------------------------------------
// Embedding (float4 vectorized)
// ---------------------------------------------------------------------------
__global__ void embed_kernel(const int* __restrict__ idx,
                             const float* __restrict__ tok,
                             const float* __restrict__ pos,
                             float* __restrict__ x) {
    int i = blockIdx.x * blockDim.x + threadIdx.x;     // element/4 index
    if (i >= BB*TT*DD/4) return;
    int d4 = i % (DD/4);
    int bt = i / (DD/4);
    int t  = bt % TT;
    float4 tv = ((const float4*)(tok + (size_t)idx[bt]*DD))[d4];
    float4 pv = ((const float4*)(pos + (size_t)t*DD))[d4];
    tv.x += pv.x; tv.y += pv.y; tv.z += pv.z; tv.w += pv.w;
    ((float4*)x)[i] = tv;
}

// ---------------------------------------------------------------------------
// LayerNorm fp32 -> bf16 hi/lo planes. 192 threads, one float4 per thread.
// ---------------------------------------------------------------------------
__global__ void ln_planes(const float* __restrict__ in,
                          __nv_bfloat16* __restrict__ oh,
                          __nv_bfloat16* __restrict__ ol,
                          const float* __restrict__ gw, const float* __restrict__ bw) {
    int row = blockIdx.x;
    const float4* x4 = (const float4*)(in + (size_t)row*DD);
    int tid = threadIdx.x;        // 0..191

    float4 v = x4[tid];
    float s  = v.x + v.y + v.z + v.w;
    float s2 = v.x*v.x + v.y*v.y + v.z*v.z + v.w*v.w;
    #pragma unroll
    for (int o = 16; o; o >>= 1) {
        s  += __shfl_xor_sync(0xffffffffu, s,  o);
        s2 += __shfl_xor_sync(0xffffffffu, s2, o);
    }
    __shared__ float r1[6], r2[6];
    __shared__ float smean, sinv;
    int w = tid >> 5;
    if ((tid & 31) == 0) { r1[w] = s; r2[w] = s2; }
    __syncthreads();
    if (tid == 0) {
        float a = 0.f, b2 = 0.f;
        #pragma unroll
        for (int i = 0; i < 6; i++) { a += r1[i]; b2 += r2[i]; }
        float mean = a / DD;
        float var  = b2 / DD - mean*mean;
        smean = mean;
        sinv  = rsqrtf(var + 1e-5f);
    }
    __syncthreads();
    float mean = smean, inv = sinv;
    float4 gv = ((const float4*)gw)[tid];
    float4 bv = ((const float4*)bw)[tid];
    float y0 = (v.x - mean) * inv * gv.x + bv.x;
    float y1 = (v.y - mean) * inv * gv.y + bv.y;
    float y2 = (v.z - mean) * inv * gv.z + bv.z;
    float y3 = (v.w - mean) * inv * gv.w + bv.w;
    size_t off = (size_t)row*DD + tid*4;
    uint32_t h0, l0, h1, l1;
    split2pack(y0, y1, h0, l0);
    split2pack(y2, y3, h1, l1);
    *(uint32_t*)(oh + off)     = h0;
    *(uint32_t*)(oh + off + 2) = h1;
    *(uint32_t*)(ol + off)     = l0;
    *(uint32_t*)(ol + off + 2) = l1;
}

// LayerNorm fp32 -> single fp16 plane (final LN, feeds LM head). 192 threads.
__global__ void ln_f16(const float* __restrict__ in,
                       __half* __restrict__ o16,
                       const float* __restrict__ gw, const float* __restrict__ bw) {
    int row = blockIdx.x;
    const float4* x4 = (const float4*)(in + (size_t)row*DD);
    int tid = threadIdx.x;

    float4 v = x4[tid];
    float s  = v.x + v.y + v.z + v.w;
    float s2 = v.x*v.x + v.y*v.y + v.z*v.z + v.w*v.w;
    #pragma unroll
    for (int o = 16; o; o >>= 1) {
        s  += __shfl_xor_sync(0xffffffffu, s,  o);
        s2 += __shfl_xor_sync(0xffffffffu, s2, o);
    }
    __shared__ float r1[6], r2[6];
    __shared__ float smean, sinv;
    int w = tid >> 5;
    if ((tid & 31) == 0) { r1[w] = s; r2[w] = s2; }
    __syncthreads();
    if (tid == 0) {
        float a = 0.f, b2 = 0.f;
        #pragma unroll
        for (int i = 0; i < 6; i++) { a += r1[i]; b2 += r2[i]; }
        float mean = a / DD;
        float var  = b2 / DD - mean*mean;
        smean = mean;
        sinv  = rsqrtf(var + 1e-5f);
    }
    __syncthreads();
    float mean = smean, inv = sinv;
    float4 gv = ((const float4*)gw)[tid];
    float4 bv = ((const float4*)bw)[tid];
    __half2 p0 = __floats2half2_rn((v.x - mean) * inv * gv.x + bv.x,
                                   (v.y - mean) * inv * gv.y + bv.y);
    __half2 p1 = __floats2half2_rn((v.z - mean) * inv * gv.z + bv.z,
                                   (v.w - mean) * inv * gv.w + bv.w);
    size_t off = (size_t)row*DD + tid*4;
    *(__half2*)(o16 + off)     = p0;
    *(__half2*)(o16 + off + 2) = p1;
}

// ---------------------------------------------------------------------------
// Flash attention (causal), split-bf16 3-term. 3-deep KV ring, ONE sync/iter.
// q is pre-scaled by 0.125 in the QKV epilogue.
// ---------------------------------------------------------------------------
#define FA_SMEM 114688
__global__ __launch_bounds__(128)
void flash_attn(const __nv_bfloat16* __restrict__ qh, const __nv_bfloat16* __restrict__ ql,
                const __nv_bfloat16* __restrict__ kh, const __nv_bfloat16* __restrict__ kl,
                const __nv_bfloat16* __restrict__ vh, const __nv_bfloat16* __restrict__ vl,
                __nv_bfloat16* __restrict__ oh, __nv_bfloat16* __restrict__ ol) {
    int bh = blockIdx.y;
    int b = bh / HH, h = bh % HH;
    int qt = (TT/64 - 1) - blockIdx.x;

    extern __shared__ __align__(16) uint8_t fsm[];
    uint32_t smQ = (uint32_t)__cvta_generic_to_shared(fsm);
    uint32_t smK = smQ + 16384;
    uint32_t smV = smQ + 65536;

    int tid = threadIdx.x;
    int lane = tid & 31, warp = tid >> 5;
    int lq = lane & 15, l4 = lane >> 4, g = lane >> 2, c2 = (lane & 3) * 2;

    const size_t bq = (size_t)b * TT;
    const int hc = h * 64;

    #pragma unroll
    for (int j = 0; j < 8; j++) {
        int id = tid + j * 128;
        int pl = id >> 9, rem = id & 511;
        int ck = rem >> 8, r = (rem >> 2) & 63, c = rem & 3;
        const __nv_bfloat16* src = (pl ? ql : qh) + (bq + qt*64 + r) * DD + hc + ck*32 + c*8;
        cpa16(smQ + pl*8192 + ck*4096 + swzc(r, c), src);
    }

    auto load_kv = [&](int kt) {
        uint32_t kb = smK + (kt % 3) * 16384;
        uint32_t vb = smV + (kt % 3) * 16384;
        #pragma unroll
        for (int j = 0; j < 16; j++) {
            int id = tid + j * 128;
            int isV = id >> 10;
            int q = id & 1023;
            int pl = q >> 9, rem = q & 511;
            int ck = rem >> 8, r = (rem >> 2) & 63, c = rem & 3;
            if (!isV) {
                const __nv_bfloat16* src = (pl ? kl : kh) + (bq + kt*64 + r) * DD + hc + ck*32 + c*8;
                cpa16(kb + pl*8192 + ck*4096 + swzc(r, c), src);
            } else {
                const __nv_bfloat16* src = (pl ? vl : vh) + ((size_t)b * DD + hc + r) * TT + kt*64 + ck*32 + c*8;
                cpa16(vb + pl*8192 + ck*4096 + swzc(r, c), src);
            }
        }
        cp_commit();
    };

    load_kv(0);

    float oacc[8][4];
    #pragma unroll
    for (int i = 0; i < 8; i++)
        #pragma unroll
        for (int e = 0; e < 4; e++) oacc[i][e] = 0.f;
    float mA = -1e30f, mB = -1e30f, lA = 0.f, lB = 0.f;

    for (int kt = 0; kt <= qt; kt++) {
        if (kt < qt) { load_kv(kt + 1); cp_wait1(); } else { cp_wait0(); }
        __syncthreads();
        uint32_t kb = smK + (kt % 3) * 16384;
        uint32_t vb = smV + (kt % 3) * 16384;

        float sacc[8][4];
        #pragma unroll
        for (int i = 0; i < 8; i++)
            #pragma unroll
            for (int e = 0; e < 4; e++) sacc[i][e] = 0.f;

        #pragma unroll
        for (int ks = 0; ks < 4; ks++) {
            int quarter = (ks & 1) * 2 + l4;
            int rQ = warp * 16 + lq;
            uint32_t offQ = (uint32_t)((ks >> 1) * 4096 + rQ * 64 + ((quarter ^ ((rQ >> 1) & 3)) << 4));
            uint32_t aqh[4], aql[4];
            ldsm4(aqh[0], aqh[1], aqh[2], aqh[3], smQ + offQ);
            ldsm4(aql[0], aql[1], aql[2], aql[3], smQ + 8192 + offQ);
            #pragma unroll
            for (int nb = 0; nb < 4; nb++) {
                int rK = nb * 16 + lq;
                uint32_t offK = (uint32_t)((ks >> 1) * 4096 + rK * 64 + ((quarter ^ ((rK >> 1) & 3)) << 4));
                uint32_t bh4[4], bl4[4];
                ldsm4(bh4[0], bh4[1], bh4[2], bh4[3], kb + offK);
                ldsm4(bl4[0], bl4[1], bl4[2], bl4[3], kb + 8192 + offK);
                mma16816(sacc[2*nb],   aqh, bh4[0], bh4[2]);
                mma16816(sacc[2*nb],   aqh, bl4[0], bl4[2]);
                mma16816(sacc[2*nb],   aql, bh4[0], bh4[2]);
                mma16816(sacc[2*nb+1], aqh, bh4[1], bh4[3]);
                mma16816(sacc[2*nb+1], aqh, bl4[1], bl4[3]);
                mma16816(sacc[2*nb+1], aql, bh4[1], bh4[3]);
            }
        }

        if (kt == qt) {
            int r0 = qt * 64 + warp * 16 + g;
            #pragma unroll
            for (int i = 0; i < 8; i++)
                #pragma unroll
                for (int e = 0; e < 4; e++) {
                    int t_g = kt * 64 + i * 8 + c2 + (e & 1);
                    int row = r0 + ((e >> 1) << 3);
                    if (t_g > row) sacc[i][e] = -1e30f;
                }
        }

        float nmA = -1e30f, nmB = -1e30f;
        #pragma unroll
        for (int i = 0; i < 8; i++) {
            nmA = fmaxf(nmA, fmaxf(sacc[i][0], sacc[i][1]));
            nmB = fmaxf(nmB, fmaxf(sacc[i][2], sacc[i][3]));
        }
        nmA = fmaxf(nmA, __shfl_xor_sync(0xffffffffu, nmA, 1));
        nmA = fmaxf(nmA, __shfl_xor_sync(0xffffffffu, nmA, 2));
        nmB = fmaxf(nmB, __shfl_xor_sync(0xffffffffu, nmB, 1));
        nmB = fmaxf(nmB, __shfl_xor_sync(0xffffffffu, nmB, 2));
        float mnA = fmaxf(mA, nmA), mnB = fmaxf(mB, nmB);
        float corrA = expf(mA - mnA), corrB = expf(mB - mnB);
        mA = mnA; mB = mnB;

        float sA = 0.f, sB = 0.f;
        #pragma unroll
        for (int i = 0; i < 8; i++) {
            float p0 = expf(sacc[i][0] - mnA);
            float p1 = expf(sacc[i][1] - mnA);
            float p2 = expf(sacc[i][2] - mnB);
            float p3 = expf(sacc[i][3] - mnB);
            sacc[i][0] = p0; sacc[i][1] = p1; sacc[i][2] = p2; sacc[i][3] = p3;
            sA += p0 + p1; sB += p2 + p3;
        }
        sA += __shfl_xor_sync(0xffffffffu, sA, 1);
        sA += __shfl_xor_sync(0xffffffffu, sA, 2);
        sB += __shfl_xor_sync(0xffffffffu, sB, 1);
        sB += __shfl_xor_sync(0xffffffffu, sB, 2);
        lA = lA * corrA + sA;
        lB = lB * corrB + sB;
        #pragma unroll
        for (int i = 0; i < 8; i++) {
            oacc[i][0] *= corrA; oacc[i][1] *= corrA;
            oacc[i][2] *= corrB; oacc[i][3] *= corrB;
        }

        #pragma unroll
        for (int j2 = 0; j2 < 4; j2++) {
            uint32_t pah[4], pal[4];
            split2pack(sacc[2*j2][0],   sacc[2*j2][1],   pah[0], pal[0]);
            split2pack(sacc[2*j2][2],   sacc[2*j2][3],   pah[1], pal[1]);
            split2pack(sacc[2*j2+1][0], sacc[2*j2+1][1], pah[2], pal[2]);
            split2pack(sacc[2*j2+1][2], sacc[2*j2+1][3], pah[3], pal[3]);
            int quarter = (j2 & 1) * 2 + l4;
            #pragma unroll
            for (int nb = 0; nb < 4; nb++) {
                int rV = nb * 16 + lq;
                uint32_t off = (uint32_t)((j2 >> 1) * 4096 + rV * 64 + ((quarter ^ ((rV >> 1) & 3)) << 4));
                uint32_t vh4[4], vl4[4];
                ldsm4(vh4[0], vh4[1], vh4[2], vh4[3], vb + off);
                ldsm4(vl4[0], vl4[1], vl4[2], vl4[3], vb + 8192 + off);
                mma16816(oacc[2*nb],   pah, vh4[0], vh4[2]);
                mma16816(oacc[2*nb],   pah, vl4[0], vl4[2]);
                mma16816(oacc[2*nb],   pal, vh4[0], vh4[2]);
                mma16816(oacc[2*nb+1], pah, vh4[1], vh4[3]);
                mma16816(oacc[2*nb+1], pah, vl4[1], vl4[3]);
                mma16816(oacc[2*nb+1], pal, vh4[1], vh4[3]);
            }
        }
    }

    float rA = 1.f / lA, rB = 1.f / lB;
    size_t row0 = bq + (size_t)qt * 64 + warp * 16 + g;
    #pragma unroll
    for (int i = 0; i < 8; i++) {
        int col = hc + i * 8 + c2;
        uint32_t hi, lo;
        split2pack(oacc[i][0] * rA, oacc[i][1] * rA, hi, lo);
        *(uint32_t*)(oh + row0 * DD + col) = hi;
        *(uint32_t*)(ol + row0 * DD + col) = lo;
        split2pack(oacc[i][2] * rB, oacc[i][3] * rB, hi, lo);
        *(uint32_t*)(oh + (row0 + 8) * DD + col) = hi;
        *(uint32_t*)(ol + (row0 + 8) * DD + col) = lo;
    }
}

// ---------------------------------------------------------------------------
// Dense split-bf16 GEMM with tile-stride loop (wave-tail elimination).
//   Block tile 128x64xK32; 8 warps (4x2); 3-stage cp.async ring, 1 sync/tile.
//   1-D grid; CTA processes tiles t, t+gridDim.x, ... ; t -> (t%ntx, t/ntx).
//   Cross-tile smem safety: nk (=K/32) is always a multiple of 3 here, so a
//   tile's final reads hit ring slot 2 while the next tile's prologue writes
//   slots 0,1; the kb=0 barrier orders the rest.
//   mode 0: fp32 out; mode 1: planes out; mode 2: vT planes out;
//   mode 3: QKV routing by N-segment (seg0->q planes *0.125, seg1->k, seg2->vT).
// ---------------------------------------------------------------------------
__global__ __launch_bounds__(256, 3)
void gemm_bf16(const __nv_bfloat16* __restrict__ Ah, const __nv_bfloat16* __restrict__ Al,
               int lda,
               const __nv_bfloat16* __restrict__ Bh, const __nv_bfloat16* __restrict__ Bl,
               int ldb,
               int K, int mode, int ntiles, int ntx,
               float* __restrict__ C, int ldc,
               __nv_bfloat16* __restrict__ Ch, __nv_bfloat16* __restrict__ Cl, int ldcp,
               __nv_bfloat16* __restrict__ Kh, __nv_bfloat16* __restrict__ Kl,
               const float* __restrict__ bias, const float* __restrict__ resid,
               int relu) {
    __shared__ __align__(16) uint8_t smbuf[3 * 24576];
    uint32_t smbase = (uint32_t)__cvta_generic_to_shared(smbuf);

    int tid = threadIdx.x;
    int lane = tid & 31, warp = tid >> 5;
    int wm = warp & 3, wn = warp >> 2;
    int nk = K / 32;

    for (int t = blockIdx.x; t < ntiles; t += gridDim.x) {
        int bn = (t % ntx) * 64;
        int bm = (t / ntx) * 128;

        auto issue = [&](int kb) {
            int k0 = kb * 32;
            uint32_t base = smbase + (kb % 3) * 24576;
            #pragma unroll
            for (int j = 0; j < 4; j++) {
                int lin = tid + j * 256;
                int pl = lin >> 9, rc = lin & 511, r = rc >> 2, c = rc & 3;
                const __nv_bfloat16* src = (pl ? Al : Ah) + (long long)(bm + r) * lda + k0 + c * 8;
                cpa16(base + pl * 8192 + swzc(r, c), src);
            }
            #pragma unroll
            for (int j = 0; j < 2; j++) {
                int lin = tid + j * 256;
                int pl = lin >> 8, rc = lin & 255, r = rc >> 2, c = rc & 3;
                const __nv_bfloat16* src = (pl ? Bl : Bh) + (long long)(bn + r) * ldb + k0 + c * 8;
                cpa16(base + 16384 + pl * 4096 + swzc(r, c), src);
            }
            cp_commit();
        };

        float acc[2][4][4];
        #pragma unroll
        for (int i = 0; i < 2; i++)
            #pragma unroll
            for (int j = 0; j < 4; j++)
                #pragma unroll
                for (int e = 0; e < 4; e++) acc[i][j][e] = 0.f;

        issue(0);
        issue(1);

        for (int kb = 0; kb < nk; kb++) {
            if (kb + 1 < nk) cp_waitg<1>(); else cp_waitg<0>();
            __syncthreads();
            if (kb + 2 < nk) issue(kb + 2);
            uint32_t base = smbase + (kb % 3) * 24576;

            #pragma unroll
            for (int ks = 0; ks < 2; ks++) {
                uint32_t ah[2][4], al[2][4], bh[2][4], bl[2][4];
                int chunk = ks * 2 + (lane >> 4);
                int rowA0 = wm * 32 + (lane & 15);
                #pragma unroll
                for (int mm = 0; mm < 2; mm++) {
                    int r = rowA0 + mm * 16;
                    uint32_t off = (uint32_t)(r * 64 + ((chunk ^ ((r >> 1) & 3)) << 4));
                    ldsm4(ah[mm][0], ah[mm][1], ah[mm][2], ah[mm][3], base + off);
                    ldsm4(al[mm][0], al[mm][1], al[mm][2], al[mm][3], base + 8192 + off);
                }
                int rowB0 = wn * 32 + (lane & 15);
                #pragma unroll
                for (int nb = 0; nb < 2; nb++) {
                    int r = rowB0 + nb * 16;
                    uint32_t off = (uint32_t)(r * 64 + ((chunk ^ ((r >> 1) & 3)) << 4));
                    ldsm4(bh[nb][0], bh[nb][1], bh[nb][2], bh[nb][3], base + 16384 + off);
                    ldsm4(bl[nb][0], bl[nb][1], bl[nb][2], bl[nb][3], base + 20480 + off);
                }
                #pragma unroll
                for (int mm = 0; mm < 2; mm++) {
                    #pragma unroll
                    for (int nf = 0; nf < 4; nf++) {
                        uint32_t b0h = bh[nf >> 1][nf & 1], b1h = bh[nf >> 1][(nf & 1) + 2];
                        uint32_t b0l = bl[nf >> 1][nf & 1], b1l = bl[nf >> 1][(nf & 1) + 2];
                        mma16816(acc[mm][nf], ah[mm], b0h, b1h);
                        mma16816(acc[mm][nf], ah[mm], b0l, b1l);
                        mma16816(acc[mm][nf], al[mm], b0h, b1h);
                    }
                }
            }
        }

        // ---- epilogue (mode-3 routing resolved first) ----
        int bnc = bn;
        __nv_bfloat16 *Oh = Ch, *Ol = Cl;
        int emode = mode;
        float escale = 1.f;
        if (mode == 3) {
            int seg = bn / DD;
            bnc = bn - seg * DD;
            if (seg == 0)      { Oh = Ch; Ol = Cl; emode = 1; escale = 0.125f; }
            else if (seg == 1) { Oh = Kh; Ol = Kl; emode = 1; }
            else               { emode = 2; }
        }

        int ml = lane >> 2, nl = (lane & 3) * 2;
        #pragma unroll
        for (int mm = 0; mm < 2; mm++) {
            #pragma unroll
            for (int nf = 0; nf < 4; nf++) {
                int col = bnc + wn * 32 + nf * 8 + nl;
                float bx = 0.f, by = 0.f;
                if (bias) { float2 bb = *(const float2*)(bias + col); bx = bb.x; by = bb.y; }
                int r0 = bm + wm * 32 + mm * 16 + ml;
                #pragma unroll
                for (int hh = 0; hh < 2; hh++) {
                    int r = r0 + hh * 8;
                    float vx = acc[mm][nf][hh * 2 + 0] + bx;
                    float vy = acc[mm][nf][hh * 2 + 1] + by;
                    if (emode == 0) {
                        long long off = (long long)r * ldc + col;
                        if (resid) {
                            float2 rr = *(const float2*)(resid + off);
                            vx += rr.x; vy += rr.y;
                        }
                        if (relu) { vx = fmaxf(vx, 0.f); vy = fmaxf(vy, 0.f); }
                        float2 v; v.x = vx; v.y = vy;
                        *(float2*)(C + off) = v;
                    } else if (emode == 1) {
                        if (relu) { vx = fmaxf(vx, 0.f); vy = fmaxf(vy, 0.f); }
                        vx *= escale; vy *= escale;
                        long long off = (long long)r * ldcp + col;
                        uint32_t hi, lo;
                        split2pack(vx, vy, hi, lo);
                        *(uint32_t*)(Oh + off) = hi;
                        *(uint32_t*)(Ol + off) = lo;
                    } else { // emode 2: vT[b][col][t], r = b*TT + t
                        int b = r >> 10, tt = r & 1023;
                        long long off = ((long long)b * DD + col) * TT + tt;
                        __nv_bfloat16 h0, l0, h1, l1;
                        split1(vx, h0, l0);
                        split1(vy, h1, l1);
                        __nv_bfloat16* th = (mode == 2) ? Ch : g_vT_hi;
                        __nv_bfloat16* tl = (mode == 2) ? Cl : g_vT_lo;
                        th[off] = h0;       tl[off] = l0;
                        th[off + TT] = h1;  tl[off + TT] = l1;
                    }
                }
            }
        }
    }
}

// ---------------------------------------------------------------------------
// LM head GEMM: logits = h16 @ wlm16^T + bias, single fp16 plane each side.
//   Grid (M-tiles=32 fastest, N-tiles=500) for B reuse in L2.
//   Block tile 128x64xK32; 8 warps (4x2); 3-stage cp.async ring (36KB smem).
// ---------------------------------------------------------------------------
__global__ __launch_bounds__(256, 3)
void gemm_lm(const __half* __restrict__ Ah,
             const __half* __restrict__ Bh,
             float* __restrict__ C, const float* __restrict__ bias) {
    int bm = blockIdx.x * 128;    // M fastest-varying
    int bn = blockIdx.y * 64;

    __shared__ __align__(16) uint8_t smbuf[3 * 12288];  // A 8K | B 4K per stage
    uint32_t smbase = (uint32_t)__cvta_generic_to_shared(smbuf);

    int tid = threadIdx.x;
    int lane = tid & 31, warp = tid >> 5;
    int wm = warp & 3, wn = warp >> 2;

    const int nk = DD / 32;   // 24

    auto issue = [&](int kb) {
        int k0 = kb * 32;
        uint32_t base = smbase + (kb % 3) * 12288;
        #pragma unroll
        for (int j = 0; j < 2; j++) {           // A: 128 rows x 4 chunks = 512
            int lin = tid + j * 256;
            int r = lin >> 2, c = lin & 3;
            cpa16(base + swzc(r, c), Ah + (long long)(bm + r) * DD + k0 + c * 8);
        }
        {                                        // B: 64 rows x 4 chunks = 256
            int r = tid >> 2, c = tid & 3;
            cpa16(base + 8192 + swzc(r, c), Bh + (long long)(bn + r) * DD + k0 + c * 8);
        }
        cp_commit();
    };

    float acc[2][4][4];
    #pragma unroll
    for (int i = 0; i < 2; i++)
        #pragma unroll
        for (int j = 0; j < 4; j++)
            #pragma unroll
            for (int e = 0; e < 4; e++) acc[i][j][e] = 0.f;

    issue(0);
    issue(1);

    for (int kb = 0; kb < nk; kb++) {
        if (kb + 1 < nk) cp_waitg<1>(); else cp_waitg<0>();
        __syncthreads();
        if (kb + 2 < nk) issue(kb + 2);
        uint32_t base = smbase + (kb % 3) * 12288;

        #pragma unroll
        for (int ks = 0; ks < 2; ks++) {
            uint32_t ah[2][4], bh[2][4];
            int chunk = ks * 2 + (lane >> 4);
            int rowA0 = wm * 32 + (lane & 15);
            #pragma unroll
            for (int mm = 0; mm < 2; mm++) {
                int r = rowA0 + mm * 16;
                uint32_t off = (uint32_t)(r * 64 + ((chunk ^ ((r >> 1) & 3)) << 4));
                ldsm4(ah[mm][0], ah[mm][1], ah[mm][2], ah[mm][3], base + off);
            }
            int rowB0 = wn * 32 + (lane & 15);
            #pragma unroll
            for (int nb = 0; nb < 2; nb++) {
                int r = rowB0 + nb * 16;
                uint32_t off = (uint32_t)(r * 64 + ((chunk ^ ((r >> 1) & 3)) << 4));
                ldsm4(bh[nb][0], bh[nb][1], bh[nb][2], bh[nb][3], base + 8192 + off);
            }
            #pragma unroll
            for (int mm = 0; mm < 2; mm++) {
                #pragma unroll
                for (int nf = 0; nf < 4; nf++) {
                    uint32_t b0h = bh[nf >> 1][nf & 1], b1h = bh[nf >> 1][(nf & 1) + 2];
                    mma16816h(acc[mm][nf], ah[mm], b0h, b1h);
                }
            }
        }
    }

    int ml = lane >> 2, nl = (lane & 3) * 2;
    #pragma unroll
    for (int mm = 0; mm < 2; mm++) {
        #pragma unroll
        for (int nf = 0; nf < 4; nf++) {
            int col = bn + wn * 32 + nf * 8 + nl;
            float2 bb = *(const float2*)(bias + col);
            int r0 = bm + wm * 32 + mm * 16 + ml;
            #pragma unroll
            for (int hh = 0; hh < 2; hh++) {
                int r = r0 + hh * 8;
                float2 v;
                v.x = acc[mm][nf][hh * 2 + 0] + bb.x;
                v.y = acc[mm][nf][hh * 2 + 1] + bb.y;
                *(float2*)(C + (long long)r * VV + col) = v;
            }
        }
    }
}

// ---------------------------------------------------------------------------
// Host orchestration
// ---------------------------------------------------------------------------
#define GETSYM(p, sym) cudaGetSymbolAddress((void**)&p, sym)

extern "C" void kernel_launch(void* const* d_in, const int* in_sizes, int n_in,
                              void* d_out, int out_size) {
    const int*   idx    = (const int*)  d_in[0];
    const float* tok    = (const float*)d_in[1];
    const float* pos    = (const float*)d_in[2];
    const float* wq     = (const float*)d_in[3];
    const float* wk     = (const float*)d_in[4];
    const float* wv     = (const float*)d_in[5];
    const float* wo     = (const float*)d_in[6];
    const float* bo     = (const float*)d_in[7];
    const float* ln1_g  = (const float*)d_in[8];
    const float* ln1_b  = (const float*)d_in[9];
    const float* ln2_g  = (const float*)d_in[10];
    const float* ln2_b  = (const float*)d_in[11];
    const float* w1     = (const float*)d_in[12];
    const float* b1     = (const float*)d_in[13];
    const float* w2     = (const float*)d_in[14];
    const float* b2     = (const float*)d_in[15];
    const float* lnf_g  = (const float*)d_in[16];
    const float* lnf_b  = (const float*)d_in[17];
    const float* w_lm   = (const float*)d_in[18];
    const float* b_lm   = (const float*)d_in[19];

    float *x;
    GETSYM(x, g_x);
    __nv_bfloat16 *h_hi,*h_lo,*q_hi,*q_lo,*k_hi,*k_lo,*vT_hi,*vT_lo,*o_hi,*o_lo,
                  *m_hi,*m_lo,
                  *wqkvT_hi,*wqkvT_lo,*woT_hi,*woT_lo,
                  *w1T_hi,*w1T_lo,*w2T_hi,*w2T_lo;
    __half *wlm16, *h16;
    GETSYM(h_hi, g_h_hi);   GETSYM(h_lo, g_h_lo);
    GETSYM(q_hi, g_q_hi);   GETSYM(q_lo, g_q_lo);
    GETSYM(k_hi, g_k_hi);   GETSYM(k_lo, g_k_lo);
    GETSYM(vT_hi, g_vT_hi); GETSYM(vT_lo, g_vT_lo);
    GETSYM(o_hi, g_o_hi);   GETSYM(o_lo, g_o_lo);
    GETSYM(m_hi, g_m_hi);   GETSYM(m_lo, g_m_lo);
    GETSYM(wqkvT_hi, g_wqkvT_hi); GETSYM(wqkvT_lo, g_wqkvT_lo);
    GETSYM(woT_hi, g_woT_hi); GETSYM(woT_lo, g_woT_lo);
    GETSYM(w1T_hi, g_w1T_hi); GETSYM(w1T_lo, g_w1T_lo);
    GETSYM(w2T_hi, g_w2T_hi); GETSYM(w2T_lo, g_w2T_lo);
    GETSYM(wlm16, g_wlm16);
    GETSYM(h16, g_h16);

    cudaFuncSetAttribute(flash_attn, cudaFuncAttributeMaxDynamicSharedMemorySize, FA_SMEM);

    const int ROWS = BB * TT;
    dim3 tb(32, 8);
    const long long QKV_OS = (long long)D3 * DD;

    transpose_split<<<dim3(DD/32, DD/32, LL), tb>>>(wq, wqkvT_hi,            wqkvT_lo,            DD, DD, QKV_OS);
    transpose_split<<<dim3(DD/32, DD/32, LL), tb>>>(wk, wqkvT_hi + DD*DD,    wqkvT_lo + DD*DD,    DD, DD, QKV_OS);
    transpose_split<<<dim3(DD/32, DD/32, LL), tb>>>(wv, wqkvT_hi + 2*DD*DD,  wqkvT_lo + 2*DD*DD,  DD, DD, QKV_OS);
    transpose_split<<<dim3(DD/32, DD/32, LL), tb>>>(wo, woT_hi, woT_lo, DD, DD, (long long)DD*DD);
    transpose_split<<<dim3(D4/32, DD/32, LL), tb>>>(w1, w1T_hi, w1T_lo, DD, D4, (long long)D4*DD);
    transpose_split<<<dim3(DD/32, D4/32, LL), tb>>>(w2, w2T_hi, w2T_lo, D4, DD, (long long)DD*D4);
    transpose_f16<<<dim3(VV/32, DD/32, 1), tb>>>(w_lm, wlm16, DD, VV);

    embed_kernel<<<(BB*TT*DD/4 + 255)/256, 256>>>(idx, tok, pos, x);

    // tile counts (ntx = N tiles, fastest)
    const int tQKV_x = D3/64,  tQKV = tQKV_x * (ROWS/128);   // 36*32 = 1152
    const int tPrj_x = DD/64,  tPrj = tPrj_x * (ROWS/128);   // 12*32 = 384
    const int tMlp_x = D4/64,  tMlp = tMlp_x * (ROWS/128);   // 48*32 = 1536
    dim3 gFA  (TT/64,  BB*HH);               // (16, 48)
    dim3 gLM  (ROWS/128, VV/64);             // (32, 500)

    int gQKV = tQKV < PERSIST ? tQKV : PERSIST;
    int gPrj = tPrj < PERSIST ? tPrj : PERSIST;
    int gMlp = tMlp < PERSIST ? tMlp : PERSIST;

    for (int l = 0; l < LL; l++) {
        size_t wqkvl = (size_t)l * D3 * DD;
        size_t wl    = (size_t)l * DD * DD;
        size_t w1l   = (size_t)l * D4 * DD;
        size_t w2l   = (size_t)l * DD * D4;

        ln_planes<<<ROWS, 192>>>(x, h_hi, h_lo, ln1_g + l*DD, ln1_b + l*DD);

        gemm_bf16<<<gQKV, 256>>>(h_hi, h_lo, DD,
                                 wqkvT_hi + wqkvl, wqkvT_lo + wqkvl, DD,
                                 DD, 3, tQKV, tQKV_x, nullptr, 0,
                                 q_hi, q_lo, DD,
                                 k_hi, k_lo,
                                 nullptr, nullptr, 0);

        flash_attn<<<gFA, 128, FA_SMEM>>>(q_hi, q_lo, k_hi, k_lo, vT_hi, vT_lo, o_hi, o_lo);

        gemm_bf16<<<gPrj, 256>>>(o_hi, o_lo, DD, woT_hi + wl, woT_lo + wl, DD,
                                 DD, 0, tPrj, tPrj_x, x, DD, nullptr, nullptr, 0,
                                 nullptr, nullptr,
                                 bo + l*DD, x, 0);

        ln_planes<<<ROWS, 192>>>(x, h_hi, h_lo, ln2_g + l*DD, ln2_b + l*DD);
        gemm_bf16<<<gMlp, 256>>>(h_hi, h_lo, DD, w1T_hi + w1l, w1T_lo + w1l, DD,
                                 DD, 1, tMlp, tMlp_x, nullptr, 0, m_hi, m_lo, D4,
                                 nullptr, nullptr,
                                 b1 + (size_t)l*D4, nullptr, 1 /*relu*/);
        gemm_bf16<<<gPrj, 256>>>(m_hi, m_lo, D4, w2T_hi + w2l, w2T_lo + w2l, D4,
                                 D4, 0, tPrj, tPrj_x, x, DD, nullptr, nullptr, 0,
                                 nullptr, nullptr,
                                 b2 + l*DD, x, 0);
    }

    ln_f16<<<ROWS, 192>>>(x, h16, lnf_g, lnf_b);
    gemm_lm<<<gLM, 256>>>(h16, wlm16, (float*)d_out, b_lm);
}

// round 16
// speedup vs baseline: 1.0156x; 1.0156x over previous
#include <cuda_runtime.h>
#include <cuda_bf16.h>
#include <cuda_fp16.h>
#include <math.h>
#include <stdint.h>

// Problem constants (MiniGPT: B=4, T=1024, D=768, H=12, L=4, V=32000, HD=64)
#define BB 4
#define TT 1024
#define DD 768
#define HH 12
#define LL 4
#define VV 32000
#define HD 64
#define D4 (4*DD)
#define D3 (3*DD)

// ---------------------------------------------------------------------------
// Scratch (device globals). bf16 "planes" are (hi, lo) split pairs.
// ---------------------------------------------------------------------------
__device__ float g_x[BB*TT*DD];

#define PLANE(name, n) \
  __device__ __align__(256) __nv_bfloat16 name##_hi[n]; \
  __device__ __align__(256) __nv_bfloat16 name##_lo[n];

PLANE(g_h,  BB*TT*DD)
PLANE(g_q,  BB*TT*DD)
PLANE(g_k,  BB*TT*DD)
PLANE(g_vT, BB*TT*DD)                 // [b][d][t] transposed V
PLANE(g_o,  BB*TT*DD)
PLANE(g_m,  (size_t)BB*TT*D4)         // MLP hidden
// transposed weights [N,K]; QKV concatenated: [L][3*DD][DD]
PLANE(g_wqkvT, (size_t)LL*D3*DD)
PLANE(g_woT, LL*DD*DD)
PLANE(g_w1T, (size_t)LL*D4*DD)
PLANE(g_w2T, (size_t)LL*DD*D4)
// LM head: single-plane fp16 path (error budget measured R8/R10: ~2e-4/side)
__device__ __align__(256) __half g_wlm16[(size_t)VV*DD];
__device__ __align__(256) __half g_h16[BB*TT*DD];

// ---------------------------------------------------------------------------
// Helpers
// ---------------------------------------------------------------------------
__device__ __forceinline__ void split1(float x, __nv_bfloat16 &h, __nv_bfloat16 &l) {
    h = __float2bfloat16_rn(x);
    l = __float2bfloat16_rn(x - __bfloat162float(h));
}
__device__ __forceinline__ void split2pack(float x, float y, uint32_t &hi, uint32_t &lo) {
    __nv_bfloat16 xh, xl, yh, yl;
    split1(x, xh, xl); split1(y, yh, yl);
    hi = (uint32_t)__bfloat16_as_ushort(xh) | ((uint32_t)__bfloat16_as_ushort(yh) << 16);
    lo = (uint32_t)__bfloat16_as_ushort(xl) | ((uint32_t)__bfloat16_as_ushort(yl) << 16);
}
__device__ __forceinline__ void ldsm4(uint32_t &r0, uint32_t &r1, uint32_t &r2, uint32_t &r3, uint32_t a) {
    asm volatile("ldmatrix.sync.aligned.m8n8.x4.shared.b16 {%0,%1,%2,%3}, [%4];\n"
                 : "=r"(r0), "=r"(r1), "=r"(r2), "=r"(r3) : "r"(a));
}
__device__ __forceinline__ void mma16816(float* d, const uint32_t* a, uint32_t b0, uint32_t b1) {
    asm volatile("mma.sync.aligned.m16n8k16.row.col.f32.bf16.bf16.f32 "
                 "{%0,%1,%2,%3},{%4,%5,%6,%7},{%8,%9},{%0,%1,%2,%3};\n"
                 : "+f"(d[0]), "+f"(d[1]), "+f"(d[2]), "+f"(d[3])
                 : "r"(a[0]), "r"(a[1]), "r"(a[2]), "r"(a[3]), "r"(b0), "r"(b1));
}
__device__ __forceinline__ void mma16816h(float* d, const uint32_t* a, uint32_t b0, uint32_t b1) {
    asm volatile("mma.sync.aligned.m16n8k16.row.col.f32.f16.f16.f32 "
                 "{%0,%1,%2,%3},{%4,%5,%6,%7},{%8,%9},{%0,%1,%2,%3};\n"
                 : "+f"(d[0]), "+f"(d[1]), "+f"(d[2]), "+f"(d[3])
                 : "r"(a[0]), "r"(a[1]), "r"(a[2]), "r"(a[3]), "r"(b0), "r"(b1));
}
__device__ __forceinline__ void cpa16(uint32_t dst, const void* src) {
    asm volatile("cp.async.cg.shared.global [%0], [%1], 16;\n" :: "r"(dst), "l"(src));
}
__device__ __forceinline__ void cp_commit() { asm volatile("cp.async.commit_group;\n"); }
template<int N> __device__ __forceinline__ void cp_waitg() {
    asm volatile("cp.async.wait_group %0;\n" :: "n"(N));
}
__device__ __forceinline__ void cp_wait1() { asm volatile("cp.async.wait_group 1;\n"); }
__device__ __forceinline__ void cp_wait0() { asm volatile("cp.async.wait_group 0;\n"); }
// byte offset of 16B chunk c (0..3) in a 64B row, XOR swizzle for ldmatrix
__device__ __forceinline__ uint32_t swzc(int row, int c) {
    return (uint32_t)(row * 64 + ((c ^ ((row >> 1) & 3)) << 4));
}

// ---------------------------------------------------------------------------
// Weight prep: transpose [K,N] fp32 -> [N,K] bf16 hi/lo planes.
// Packed uint32 stores: each output slot covers 2 adjacent K elements.
// ---------------------------------------------------------------------------
__global__ void transpose_split(const float* __restrict__ in,
                                __nv_bfloat16* __restrict__ oh,
                                __nv_bfloat16* __restrict__ ol,
                                int K, int N, long long ostride) {
    in += (size_t)blockIdx.z * K * N;
    oh += (size_t)blockIdx.z * ostride;
    ol += (size_t)blockIdx.z * ostride;
    __shared__ float tile[32][33];     // tile[k_local][n_local]
    int n0 = blockIdx.x * 32, k0 = blockIdx.y * 32;
    int tx = threadIdx.x, ty = threadIdx.y;
    int tid = ty * 32 + tx;            // 0..255
    #pragma unroll
    for (int i = 0; i < 4; i++)
        tile[ty + i*8][tx] = in[(size_t)(k0 + ty + i*8) * N + n0 + tx];
    __syncthreads();
    // 512 uint32 slots = 32 n-rows x 16 k-pairs; 2 slots per thread.
    #pragma unroll
    for (int j = 0; j < 2; j++) {
        int slot = tid + j * 256;
        int n  = slot >> 4;            // 0..31
        int k2 = slot & 15;            // 0..15 (pair of k)
        float v0 = tile[2*k2][n];
        float v1 = tile[2*k2 + 1][n];
        uint32_t hi, lo;
        split2pack(v0, v1, hi, lo);
        size_t off = (size_t)(n0 + n) * K + k0 + 2*k2;
        *(uint32_t*)(oh + off) = hi;
        *(uint32_t*)(ol + off) = lo;
    }
}

// fp16 single-plane variant (LM head weights), packed __half2 stores
__global__ void transpose_f16(const float* __restrict__ in,
                              __half* __restrict__ oh,
                              int K, int N) {
    __shared__ float tile[32][33];
    int n0 = blockIdx.x * 32, k0 = blockIdx.y * 32;
    int tx = threadIdx.x, ty = threadIdx.y;
    int tid = ty * 32 + tx;
    #pragma unroll
    for (int i = 0; i < 4; i++)
        tile[ty + i*8][tx] = in[(size_t)(k0 + ty + i*8) * N + n0 + tx];
    __syncthreads();
    #pragma unroll
    for (int j = 0; j < 2; j++) {
        int slot = tid + j * 256;
        int n  = slot >> 4;
        int k2 = slot & 15;
        __half2 p = __floats2half2_rn(tile[2*k2][n], tile[2*k2 + 1][n]);
        size_t off = (size_t)(n0 + n) * K + k0 + 2*k2;
        *(__half2*)(oh + off) = p;
    }
}

// ---------------------------------------------------------------------------
// Embedding (float4 vectorized)
// ---------------------------------------------------------------------------
__global__ void embed_kernel(const int* __restrict__ idx,
                             const float* __restrict__ tok,
                             const float* __restrict__ pos,
                             float* __restrict__ x) {
    int i = blockIdx.x * blockDim.x + threadIdx.x;     // element/4 index
    if (i >= BB*TT*DD/4) return;
    int d4 = i % (DD/4);
    int bt = i / (DD/4);
    int t  = bt % TT;
    float4 tv = ((const float4*)(tok + (size_t)idx[bt]*DD))[d4];
    float4 pv = ((const float4*)(pos + (size_t)t*DD))[d4];
    tv.x += pv.x; tv.y += pv.y; tv.z += pv.z; tv.w += pv.w;
    ((float4*)x)[i] = tv;
}

// ---------------------------------------------------------------------------
// LayerNorm fp32 -> bf16 hi/lo planes. 192 threads, one float4 per thread.
// ---------------------------------------------------------------------------
__global__ void ln_planes(const float* __restrict__ in,
                          __nv_bfloat16* __restrict__ oh,
                          __nv_bfloat16* __restrict__ ol,
                          const float* __restrict__ gw, const float* __restrict__ bw) {
    int row = blockIdx.x;
    const float4* x4 = (const float4*)(in + (size_t)row*DD);
    int tid = threadIdx.x;        // 0..191

    float4 v = x4[tid];
    float s  = v.x + v.y + v.z + v.w;
    float s2 = v.x*v.x + v.y*v.y + v.z*v.z + v.w*v.w;
    #pragma unroll
    for (int o = 16; o; o >>= 1) {
        s  += __shfl_xor_sync(0xffffffffu, s,  o);
        s2 += __shfl_xor_sync(0xffffffffu, s2, o);
    }
    __shared__ float r1[6], r2[6];
    __shared__ float smean, sinv;
    int w = tid >> 5;
    if ((tid & 31) == 0) { r1[w] = s; r2[w] = s2; }
    __syncthreads();
    if (tid == 0) {
        float a = 0.f, b2 = 0.f;
        #pragma unroll
        for (int i = 0; i < 6; i++) { a += r1[i]; b2 += r2[i]; }
        float mean = a / DD;
        float var  = b2 / DD - mean*mean;
        smean = mean;
        sinv  = rsqrtf(var + 1e-5f);
    }
    __syncthreads();
    float mean = smean, inv = sinv;
    float4 gv = ((const float4*)gw)[tid];
    float4 bv = ((const float4*)bw)[tid];
    float y0 = (v.x - mean) * inv * gv.x + bv.x;
    float y1 = (v.y - mean) * inv * gv.y + bv.y;
    float y2 = (v.z - mean) * inv * gv.z + bv.z;
    float y3 = (v.w - mean) * inv * gv.w + bv.w;
    size_t off = (size_t)row*DD + tid*4;
    uint32_t h0, l0, h1, l1;
    split2pack(y0, y1, h0, l0);
    split2pack(y2, y3, h1, l1);
    *(uint32_t*)(oh + off)     = h0;
    *(uint32_t*)(oh + off + 2) = h1;
    *(uint32_t*)(ol + off)     = l0;
    *(uint32_t*)(ol + off + 2) = l1;
}

// LayerNorm fp32 -> single fp16 plane (final LN, feeds LM head). 192 threads.
__global__ void ln_f16(const float* __restrict__ in,
                       __half* __restrict__ o16,
                       const float* __restrict__ gw, const float* __restrict__ bw) {
    int row = blockIdx.x;
    const float4* x4 = (const float4*)(in + (size_t)row*DD);
    int tid = threadIdx.x;

    float4 v = x4[tid];
    float s  = v.x + v.y + v.z + v.w;
    float s2 = v.x*v.x + v.y*v.y + v.z*v.z + v.w*v.w;
    #pragma unroll
    for (int o = 16; o; o >>= 1) {
        s  += __shfl_xor_sync(0xffffffffu, s,  o);
        s2 += __shfl_xor_sync(0xffffffffu, s2, o);
    }
    __shared__ float r1[6], r2[6];
    __shared__ float smean, sinv;
    int w = tid >> 5;
    if ((tid & 31) == 0) { r1[w] = s; r2[w] = s2; }
    __syncthreads();
    if (tid == 0) {
        float a = 0.f, b2 = 0.f;
        #pragma unroll
        for (int i = 0; i < 6; i++) { a += r1[i]; b2 += r2[i]; }
        float mean = a / DD;
        float var  = b2 / DD - mean*mean;
        smean = mean;
        sinv  = rsqrtf(var + 1e-5f);
    }
    __syncthreads();
    float mean = smean, inv = sinv;
    float4 gv = ((const float4*)gw)[tid];
    float4 bv = ((const float4*)bw)[tid];
    __half2 p0 = __floats2half2_rn((v.x - mean) * inv * gv.x + bv.x,
                                   (v.y - mean) * inv * gv.y + bv.y);
    __half2 p1 = __floats2half2_rn((v.z - mean) * inv * gv.z + bv.z,
                                   (v.w - mean) * inv * gv.w + bv.w);
    size_t off = (size_t)row*DD + tid*4;
    *(__half2*)(o16 + off)     = p0;
    *(__half2*)(o16 + off + 2) = p1;
}

// ---------------------------------------------------------------------------
// Flash attention (causal), split-bf16 3-term. 3-deep KV ring, ONE sync/iter.
// q is pre-scaled by 0.125 in the QKV epilogue.
// ---------------------------------------------------------------------------
#define FA_SMEM 114688
__global__ __launch_bounds__(128)
void flash_attn(const __nv_bfloat16* __restrict__ qh, const __nv_bfloat16* __restrict__ ql,
                const __nv_bfloat16* __restrict__ kh, const __nv_bfloat16* __restrict__ kl,
                const __nv_bfloat16* __restrict__ vh, const __nv_bfloat16* __restrict__ vl,
                __nv_bfloat16* __restrict__ oh, __nv_bfloat16* __restrict__ ol) {
    int bh = blockIdx.y;
    int b = bh / HH, h = bh % HH;
    int qt = (TT/64 - 1) - blockIdx.x;

    extern __shared__ __align__(16) uint8_t fsm[];
    uint32_t smQ = (uint32_t)__cvta_generic_to_shared(fsm);
    uint32_t smK = smQ + 16384;
    uint32_t smV = smQ + 65536;

    int tid = threadIdx.x;
    int lane = tid & 31, warp = tid >> 5;
    int lq = lane & 15, l4 = lane >> 4, g = lane >> 2, c2 = (lane & 3) * 2;

    const size_t bq = (size_t)b * TT;
    const int hc = h * 64;

    #pragma unroll
    for (int j = 0; j < 8; j++) {
        int id = tid + j * 128;
        int pl = id >> 9, rem = id & 511;
        int ck = rem >> 8, r = (rem >> 2) & 63, c = rem & 3;
        const __nv_bfloat16* src = (pl ? ql : qh) + (bq + qt*64 + r) * DD + hc + ck*32 + c*8;
        cpa16(smQ + pl*8192 + ck*4096 + swzc(r, c), src);
    }

    auto load_kv = [&](int kt) {
        uint32_t kb = smK + (kt % 3) * 16384;
        uint32_t vb = smV + (kt % 3) * 16384;
        #pragma unroll
        for (int j = 0; j < 16; j++) {
            int id = tid + j * 128;
            int isV = id >> 10;
            int q = id & 1023;
            int pl = q >> 9, rem = q & 511;
            int ck = rem >> 8, r = (rem >> 2) & 63, c = rem & 3;
            if (!isV) {
                const __nv_bfloat16* src = (pl ? kl : kh) + (bq + kt*64 + r) * DD + hc + ck*32 + c*8;
                cpa16(kb + pl*8192 + ck*4096 + swzc(r, c), src);
            } else {
                const __nv_bfloat16* src = (pl ? vl : vh) + ((size_t)b * DD + hc + r) * TT + kt*64 + ck*32 + c*8;
                cpa16(vb + pl*8192 + ck*4096 + swzc(r, c), src);
            }
        }
        cp_commit();
    };

    load_kv(0);

    float oacc[8][4];
    #pragma unroll
    for (int i = 0; i < 8; i++)
        #pragma unroll
        for (int e = 0; e < 4; e++) oacc[i][e] = 0.f;
    float mA = -1e30f, mB = -1e30f, lA = 0.f, lB = 0.f;

    for (int kt = 0; kt <= qt; kt++) {
        if (kt < qt) { load_kv(kt + 1); cp_wait1(); } else { cp_wait0(); }
        __syncthreads();
        uint32_t kb = smK + (kt % 3) * 16384;
        uint32_t vb = smV + (kt % 3) * 16384;

        float sacc[8][4];
        #pragma unroll
        for (int i = 0; i < 8; i++)
            #pragma unroll
            for (int e = 0; e < 4; e++) sacc[i][e] = 0.f;

        #pragma unroll
        for (int ks = 0; ks < 4; ks++) {
            int quarter = (ks & 1) * 2 + l4;
            int rQ = warp * 16 + lq;
            uint32_t offQ = (uint32_t)((ks >> 1) * 4096 + rQ * 64 + ((quarter ^ ((rQ >> 1) & 3)) << 4));
            uint32_t aqh[4], aql[4];
            ldsm4(aqh[0], aqh[1], aqh[2], aqh[3], smQ + offQ);
            ldsm4(aql[0], aql[1], aql[2], aql[3], smQ + 8192 + offQ);
            #pragma unroll
            for (int nb = 0; nb < 4; nb++) {
                int rK = nb * 16 + lq;
                uint32_t offK = (uint32_t)((ks >> 1) * 4096 + rK * 64 + ((quarter ^ ((rK >> 1) & 3)) << 4));
                uint32_t bh4[4], bl4[4];
                ldsm4(bh4[0], bh4[1], bh4[2], bh4[3], kb + offK);
                ldsm4(bl4[0], bl4[1], bl4[2], bl4[3], kb + 8192 + offK);
                mma16816(sacc[2*nb],   aqh, bh4[0], bh4[2]);
                mma16816(sacc[2*nb],   aqh, bl4[0], bl4[2]);
                mma16816(sacc[2*nb],   aql, bh4[0], bh4[2]);
                mma16816(sacc[2*nb+1], aqh, bh4[1], bh4[3]);
                mma16816(sacc[2*nb+1], aqh, bl4[1], bl4[3]);
                mma16816(sacc[2*nb+1], aql, bh4[1], bh4[3]);
            }
        }

        if (kt == qt) {
            int r0 = qt * 64 + warp * 16 + g;
            #pragma unroll
            for (int i = 0; i < 8; i++)
                #pragma unroll
                for (int e = 0; e < 4; e++) {
                    int t_g = kt * 64 + i * 8 + c2 + (e & 1);
                    int row = r0 + ((e >> 1) << 3);
                    if (t_g > row) sacc[i][e] = -1e30f;
                }
        }

        float nmA = -1e30f, nmB = -1e30f;
        #pragma unroll
        for (int i = 0; i < 8; i++) {
            nmA = fmaxf(nmA, fmaxf(sacc[i][0], sacc[i][1]));
            nmB = fmaxf(nmB, fmaxf(sacc[i][2], sacc[i][3]));
        }
        nmA = fmaxf(nmA, __shfl_xor_sync(0xffffffffu, nmA, 1));
        nmA = fmaxf(nmA, __shfl_xor_sync(0xffffffffu, nmA, 2));
        nmB = fmaxf(nmB, __shfl_xor_sync(0xffffffffu, nmB, 1));
        nmB = fmaxf(nmB, __shfl_xor_sync(0xffffffffu, nmB, 2));
        float mnA = fmaxf(mA, nmA), mnB = fmaxf(mB, nmB);
        float corrA = expf(mA - mnA), corrB = expf(mB - mnB);
        mA = mnA; mB = mnB;

        float sA = 0.f, sB = 0.f;
        #pragma unroll
        for (int i = 0; i < 8; i++) {
            float p0 = expf(sacc[i][0] - mnA);
            float p1 = expf(sacc[i][1] - mnA);
            float p2 = expf(sacc[i][2] - mnB);
            float p3 = expf(sacc[i][3] - mnB);
            sacc[i][0] = p0; sacc[i][1] = p1; sacc[i][2] = p2; sacc[i][3] = p3;
            sA += p0 + p1; sB += p2 + p3;
        }
        sA += __shfl_xor_sync(0xffffffffu, sA, 1);
        sA += __shfl_xor_sync(0xffffffffu, sA, 2);
        sB += __shfl_xor_sync(0xffffffffu, sB, 1);
        sB += __shfl_xor_sync(0xffffffffu, sB, 2);
        lA = lA * corrA + sA;
        lB = lB * corrB + sB;
        #pragma unroll
        for (int i = 0; i < 8; i++) {
            oacc[i][0] *= corrA; oacc[i][1] *= corrA;
            oacc[i][2] *= corrB; oacc[i][3] *= corrB;
        }

        #pragma unroll
        for (int j2 = 0; j2 < 4; j2++) {
            uint32_t pah[4], pal[4];
            split2pack(sacc[2*j2][0],   sacc[2*j2][1],   pah[0], pal[0]);
            split2pack(sacc[2*j2][2],   sacc[2*j2][3],   pah[1], pal[1]);
            split2pack(sacc[2*j2+1][0], sacc[2*j2+1][1], pah[2], pal[2]);
            split2pack(sacc[2*j2+1][2], sacc[2*j2+1][3], pah[3], pal[3]);
            int quarter = (j2 & 1) * 2 + l4;
            #pragma unroll
            for (int nb = 0; nb < 4; nb++) {
                int rV = nb * 16 + lq;
                uint32_t off = (uint32_t)((j2 >> 1) * 4096 + rV * 64 + ((quarter ^ ((rV >> 1) & 3)) << 4));
                uint32_t vh4[4], vl4[4];
                ldsm4(vh4[0], vh4[1], vh4[2], vh4[3], vb + off);
                ldsm4(vl4[0], vl4[1], vl4[2], vl4[3], vb + 8192 + off);
                mma16816(oacc[2*nb],   pah, vh4[0], vh4[2]);
                mma16816(oacc[2*nb],   pah, vl4[0], vl4[2]);
                mma16816(oacc[2*nb],   pal, vh4[0], vh4[2]);
                mma16816(oacc[2*nb+1], pah, vh4[1], vh4[3]);
                mma16816(oacc[2*nb+1], pah, vl4[1], vl4[3]);
                mma16816(oacc[2*nb+1], pal, vh4[1], vh4[3]);
            }
        }
    }

    float rA = 1.f / lA, rB = 1.f / lB;
    size_t row0 = bq + (size_t)qt * 64 + warp * 16 + g;
    #pragma unroll
    for (int i = 0; i < 8; i++) {
        int col = hc + i * 8 + c2;
        uint32_t hi, lo;
        split2pack(oacc[i][0] * rA, oacc[i][1] * rA, hi, lo);
        *(uint32_t*)(oh + row0 * DD + col) = hi;
        *(uint32_t*)(ol + row0 * DD + col) = lo;
        split2pack(oacc[i][2] * rB, oacc[i][3] * rB, hi, lo);
        *(uint32_t*)(oh + (row0 + 8) * DD + col) = hi;
        *(uint32_t*)(ol + (row0 + 8) * DD + col) = lo;
    }
}

// ---------------------------------------------------------------------------
// Dense split-bf16 GEMM: C = act(A@B^T + bias [+resid])
//   Block tile 128x64xK32; 8 warps (4x2); 3-stage cp.async ring, 1 sync/tile.
//   mode 0: fp32 out; mode 1: planes out; mode 2: vT planes out;
//   mode 3: QKV routing by N-segment (seg0->q planes *0.125, seg1->k, seg2->vT).
// ---------------------------------------------------------------------------
__global__ __launch_bounds__(256, 3)
void gemm_bf16(const __nv_bfloat16* __restrict__ Ah, const __nv_bfloat16* __restrict__ Al,
               int lda,
               const __nv_bfloat16* __restrict__ Bh, const __nv_bfloat16* __restrict__ Bl,
               int ldb,
               int K, int mode,
               float* __restrict__ C, int ldc,
               __nv_bfloat16* __restrict__ Ch, __nv_bfloat16* __restrict__ Cl, int ldcp,
               __nv_bfloat16* __restrict__ Kh, __nv_bfloat16* __restrict__ Kl,
               const float* __restrict__ bias, const float* __restrict__ resid,
               int relu) {
    int bm = blockIdx.y * 128;
    int bn = blockIdx.x * 64;

    __shared__ __align__(16) uint8_t smbuf[3 * 24576];
    uint32_t smbase = (uint32_t)__cvta_generic_to_shared(smbuf);

    int tid = threadIdx.x;
    int lane = tid & 31, warp = tid >> 5;
    int wm = warp & 3, wn = warp >> 2;

    int nk = K / 32;

    auto issue = [&](int kb) {
        int k0 = kb * 32;
        uint32_t base = smbase + (kb % 3) * 24576;
        #pragma unroll
        for (int j = 0; j < 4; j++) {
            int lin = tid + j * 256;
            int pl = lin >> 9, rc = lin & 511, r = rc >> 2, c = rc & 3;
            const __nv_bfloat16* src = (pl ? Al : Ah) + (long long)(bm + r) * lda + k0 + c * 8;
            cpa16(base + pl * 8192 + swzc(r, c), src);
        }
        #pragma unroll
        for (int j = 0; j < 2; j++) {
            int lin = tid + j * 256;
            int pl = lin >> 8, rc = lin & 255, r = rc >> 2, c = rc & 3;
            const __nv_bfloat16* src = (pl ? Bl : Bh) + (long long)(bn + r) * ldb + k0 + c * 8;
            cpa16(base + 16384 + pl * 4096 + swzc(r, c), src);
        }
        cp_commit();
    };

    float acc[2][4][4];
    #pragma unroll
    for (int i = 0; i < 2; i++)
        #pragma unroll
        for (int j = 0; j < 4; j++)
            #pragma unroll
            for (int e = 0; e < 4; e++) acc[i][j][e] = 0.f;

    issue(0);
    if (nk > 1) issue(1);

    for (int kb = 0; kb < nk; kb++) {
        if (kb + 1 < nk) cp_waitg<1>(); else cp_waitg<0>();
        __syncthreads();
        if (kb + 2 < nk) issue(kb + 2);
        uint32_t base = smbase + (kb % 3) * 24576;

        #pragma unroll
        for (int ks = 0; ks < 2; ks++) {
            uint32_t ah[2][4], al[2][4], bh[2][4], bl[2][4];
            int chunk = ks * 2 + (lane >> 4);
            int rowA0 = wm * 32 + (lane & 15);
            #pragma unroll
            for (int mm = 0; mm < 2; mm++) {
                int r = rowA0 + mm * 16;
                uint32_t off = (uint32_t)(r * 64 + ((chunk ^ ((r >> 1) & 3)) << 4));
                ldsm4(ah[mm][0], ah[mm][1], ah[mm][2], ah[mm][3], base + off);
                ldsm4(al[mm][0], al[mm][1], al[mm][2], al[mm][3], base + 8192 + off);
            }
            int rowB0 = wn * 32 + (lane & 15);
            #pragma unroll
            for (int nb = 0; nb < 2; nb++) {
                int r = rowB0 + nb * 16;
                uint32_t off = (uint32_t)(r * 64 + ((chunk ^ ((r >> 1) & 3)) << 4));
                ldsm4(bh[nb][0], bh[nb][1], bh[nb][2], bh[nb][3], base + 16384 + off);
                ldsm4(bl[nb][0], bl[nb][1], bl[nb][2], bl[nb][3], base + 20480 + off);
            }
            #pragma unroll
            for (int mm = 0; mm < 2; mm++) {
                #pragma unroll
                for (int nf = 0; nf < 4; nf++) {
                    uint32_t b0h = bh[nf >> 1][nf & 1], b1h = bh[nf >> 1][(nf & 1) + 2];
                    uint32_t b0l = bl[nf >> 1][nf & 1], b1l = bl[nf >> 1][(nf & 1) + 2];
                    mma16816(acc[mm][nf], ah[mm], b0h, b1h);
                    mma16816(acc[mm][nf], ah[mm], b0l, b1l);
                    mma16816(acc[mm][nf], al[mm], b0h, b1h);
                }
            }
        }
    }

    // ---- epilogue (mode-3 routing resolved first) ----
    int bnc = bn;
    __nv_bfloat16 *Oh = Ch, *Ol = Cl;
    int emode = mode;
    float escale = 1.f;
    if (mode == 3) {
        int seg = bn / DD;
        bnc = bn - seg * DD;
        if (seg == 0)      { Oh = Ch; Ol = Cl; emode = 1; escale = 0.125f; }
        else if (seg == 1) { Oh = Kh; Ol = Kl; emode = 1; }
        else               { emode = 2; }
    }

    int ml = lane >> 2, nl = (lane & 3) * 2;
    #pragma unroll
    for (int mm = 0; mm < 2; mm++) {
        #pragma unroll
        for (int nf = 0; nf < 4; nf++) {
            int col = bnc + wn * 32 + nf * 8 + nl;
            float bx = 0.f, by = 0.f;
            if (bias) { float2 bb = *(const float2*)(bias + col); bx = bb.x; by = bb.y; }
            int r0 = bm + wm * 32 + mm * 16 + ml;
            #pragma unroll
            for (int hh = 0; hh < 2; hh++) {
                int r = r0 + hh * 8;
                float vx = acc[mm][nf][hh * 2 + 0] + bx;
                float vy = acc[mm][nf][hh * 2 + 1] + by;
                if (emode == 0) {
                    long long off = (long long)r * ldc + col;
                    if (resid) {
                        float2 rr = *(const float2*)(resid + off);
                        vx += rr.x; vy += rr.y;
                    }
                    if (relu) { vx = fmaxf(vx, 0.f); vy = fmaxf(vy, 0.f); }
                    float2 v; v.x = vx; v.y = vy;
                    *(float2*)(C + off) = v;
                } else if (emode == 1) {
                    if (relu) { vx = fmaxf(vx, 0.f); vy = fmaxf(vy, 0.f); }
                    vx *= escale; vy *= escale;
                    long long off = (long long)r * ldcp + col;
                    uint32_t hi, lo;
                    split2pack(vx, vy, hi, lo);
                    *(uint32_t*)(Oh + off) = hi;
                    *(uint32_t*)(Ol + off) = lo;
                } else { // emode 2: vT[b][col][t], r = b*TT + t
                    int b = r >> 10, t = r & 1023;
                    long long off = ((long long)b * DD + col) * TT + t;
                    __nv_bfloat16 h0, l0, h1, l1;
                    split1(vx, h0, l0);
                    split1(vy, h1, l1);
                    __nv_bfloat16* th = (mode == 2) ? Ch : g_vT_hi;
                    __nv_bfloat16* tl = (mode == 2) ? Cl : g_vT_lo;
                    th[off] = h0;       tl[off] = l0;
                    th[off + TT] = h1;  tl[off + TT] = l1;
                }
            }
        }
    }
}

// ---------------------------------------------------------------------------
// LM head GEMM: logits = h16 @ wlm16^T + bias, single fp16 plane each side.
//   Grid (M-tiles=32 fastest, N-tiles=500) for B reuse in L2.
//   Block tile 128x64xK32; 8 warps (4x2); 3-stage cp.async ring (36KB smem).
// ---------------------------------------------------------------------------
__global__ __launch_bounds__(256, 3)
void gemm_lm(const __half* __restrict__ Ah,
             const __half* __restrict__ Bh,
             float* __restrict__ C, const float* __restrict__ bias) {
    int bm = blockIdx.x * 128;    // M fastest-varying
    int bn = blockIdx.y * 64;

    __shared__ __align__(16) uint8_t smbuf[3 * 12288];  // A 8K | B 4K per stage
    uint32_t smbase = (uint32_t)__cvta_generic_to_shared(smbuf);

    int tid = threadIdx.x;
    int lane = tid & 31, warp = tid >> 5;
    int wm = warp & 3, wn = warp >> 2;

    const int nk = DD / 32;   // 24

    auto issue = [&](int kb) {
        int k0 = kb * 32;
        uint32_t base = smbase + (kb % 3) * 12288;
        #pragma unroll
        for (int j = 0; j < 2; j++) {           // A: 128 rows x 4 chunks = 512
            int lin = tid + j * 256;
            int r = lin >> 2, c = lin & 3;
            cpa16(base + swzc(r, c), Ah + (long long)(bm + r) * DD + k0 + c * 8);
        }
        {                                        // B: 64 rows x 4 chunks = 256
            int r = tid >> 2, c = tid & 3;
            cpa16(base + 8192 + swzc(r, c), Bh + (long long)(bn + r) * DD + k0 + c * 8);
        }
        cp_commit();
    };

    float acc[2][4][4];
    #pragma unroll
    for (int i = 0; i < 2; i++)
        #pragma unroll
        for (int j = 0; j < 4; j++)
            #pragma unroll
            for (int e = 0; e < 4; e++) acc[i][j][e] = 0.f;

    issue(0);
    issue(1);

    for (int kb = 0; kb < nk; kb++) {
        if (kb + 1 < nk) cp_waitg<1>(); else cp_waitg<0>();
        __syncthreads();
        if (kb + 2 < nk) issue(kb + 2);
        uint32_t base = smbase + (kb % 3) * 12288;

        #pragma unroll
        for (int ks = 0; ks < 2; ks++) {
            uint32_t ah[2][4], bh[2][4];
            int chunk = ks * 2 + (lane >> 4);
            int rowA0 = wm * 32 + (lane & 15);
            #pragma unroll
            for (int mm = 0; mm < 2; mm++) {
                int r = rowA0 + mm * 16;
                uint32_t off = (uint32_t)(r * 64 + ((chunk ^ ((r >> 1) & 3)) << 4));
                ldsm4(ah[mm][0], ah[mm][1], ah[mm][2], ah[mm][3], base + off);
            }
            int rowB0 = wn * 32 + (lane & 15);
            #pragma unroll
            for (int nb = 0; nb < 2; nb++) {
                int r = rowB0 + nb * 16;
                uint32_t off = (uint32_t)(r * 64 + ((chunk ^ ((r >> 1) & 3)) << 4));
                ldsm4(bh[nb][0], bh[nb][1], bh[nb][2], bh[nb][3], base + 8192 + off);
            }
            #pragma unroll
            for (int mm = 0; mm < 2; mm++) {
                #pragma unroll
                for (int nf = 0; nf < 4; nf++) {
                    uint32_t b0h = bh[nf >> 1][nf & 1], b1h = bh[nf >> 1][(nf & 1) + 2];
                    mma16816h(acc[mm][nf], ah[mm], b0h, b1h);
                }
            }
        }
    }

    int ml = lane >> 2, nl = (lane & 3) * 2;
    #pragma unroll
    for (int mm = 0; mm < 2; mm++) {
        #pragma unroll
        for (int nf = 0; nf < 4; nf++) {
            int col = bn + wn * 32 + nf * 8 + nl;
            float2 bb = *(const float2*)(bias + col);
            int r0 = bm + wm * 32 + mm * 16 + ml;
            #pragma unroll
            for (int hh = 0; hh < 2; hh++) {
                int r = r0 + hh * 8;
                float2 v;
                v.x = acc[mm][nf][hh * 2 + 0] + bb.x;
                v.y = acc[mm][nf][hh * 2 + 1] + bb.y;
                *(float2*)(C + (long long)r * VV + col) = v;
            }
        }
    }
}

// ---------------------------------------------------------------------------
// Host orchestration
// ---------------------------------------------------------------------------
#define GETSYM(p, sym) cudaGetSymbolAddress((void**)&p, sym)

extern "C" void kernel_launch(void* const* d_in, const int* in_sizes, int n_in,
                              void* d_out, int out_size) {
    const int*   idx    = (const int*)  d_in[0];
    const float* tok    = (const float*)d_in[1];
    const float* pos    = (const float*)d_in[2];
    const float* wq     = (const float*)d_in[3];
    const float* wk     = (const float*)d_in[4];
    const float* wv     = (const float*)d_in[5];
    const float* wo     = (const float*)d_in[6];
    const float* bo     = (const float*)d_in[7];
    const float* ln1_g  = (const float*)d_in[8];
    const float* ln1_b  = (const float*)d_in[9];
    const float* ln2_g  = (const float*)d_in[10];
    const float* ln2_b  = (const float*)d_in[11];
    const float* w1     = (const float*)d_in[12];
    const float* b1     = (const float*)d_in[13];
    const float* w2     = (const float*)d_in[14];
    const float* b2     = (const float*)d_in[15];
    const float* lnf_g  = (const float*)d_in[16];
    const float* lnf_b  = (const float*)d_in[17];
    const float* w_lm   = (const float*)d_in[18];
    const float* b_lm   = (const float*)d_in[19];

    float *x;
    GETSYM(x, g_x);
    __nv_bfloat16 *h_hi,*h_lo,*q_hi,*q_lo,*k_hi,*k_lo,*vT_hi,*vT_lo,*o_hi,*o_lo,
                  *m_hi,*m_lo,
                  *wqkvT_hi,*wqkvT_lo,*woT_hi,*woT_lo,
                  *w1T_hi,*w1T_lo,*w2T_hi,*w2T_lo;
    __half *wlm16, *h16;
    GETSYM(h_hi, g_h_hi);   GETSYM(h_lo, g_h_lo);
    GETSYM(q_hi, g_q_hi);   GETSYM(q_lo, g_q_lo);
    GETSYM(k_hi, g_k_hi);   GETSYM(k_lo, g_k_lo);
    GETSYM(vT_hi, g_vT_hi); GETSYM(vT_lo, g_vT_lo);
    GETSYM(o_hi, g_o_hi);   GETSYM(o_lo, g_o_lo);
    GETSYM(m_hi, g_m_hi);   GETSYM(m_lo, g_m_lo);
    GETSYM(wqkvT_hi, g_wqkvT_hi); GETSYM(wqkvT_lo, g_wqkvT_lo);
    GETSYM(woT_hi, g_woT_hi); GETSYM(woT_lo, g_woT_lo);
    GETSYM(w1T_hi, g_w1T_hi); GETSYM(w1T_lo, g_w1T_lo);
    GETSYM(w2T_hi, g_w2T_hi); GETSYM(w2T_lo, g_w2T_lo);
    GETSYM(wlm16, g_wlm16);
    GETSYM(h16, g_h16);

    cudaFuncSetAttribute(flash_attn, cudaFuncAttributeMaxDynamicSharedMemorySize, FA_SMEM);

    const int ROWS = BB * TT;
    dim3 tb(32, 8);
    const long long QKV_OS = (long long)D3 * DD;

    transpose_split<<<dim3(DD/32, DD/32, LL), tb>>>(wq, wqkvT_hi,            wqkvT_lo,            DD, DD, QKV_OS);
    transpose_split<<<dim3(DD/32, DD/32, LL), tb>>>(wk, wqkvT_hi + DD*DD,    wqkvT_lo + DD*DD,    DD, DD, QKV_OS);
    transpose_split<<<dim3(DD/32, DD/32, LL), tb>>>(wv, wqkvT_hi + 2*DD*DD,  wqkvT_lo + 2*DD*DD,  DD, DD, QKV_OS);
    transpose_split<<<dim3(DD/32, DD/32, LL), tb>>>(wo, woT_hi, woT_lo, DD, DD, (long long)DD*DD);
    transpose_split<<<dim3(D4/32, DD/32, LL), tb>>>(w1, w1T_hi, w1T_lo, DD, D4, (long long)D4*DD);
    transpose_split<<<dim3(DD/32, D4/32, LL), tb>>>(w2, w2T_hi, w2T_lo, D4, DD, (long long)DD*D4);
    transpose_f16<<<dim3(VV/32, DD/32, 1), tb>>>(w_lm, wlm16, DD, VV);

    embed_kernel<<<(BB*TT*DD/4 + 255)/256, 256>>>(idx, tok, pos, x);

    dim3 gQKV (D3/64,  ROWS/128);            // (36, 32)
    dim3 gProj(DD/64,  ROWS/128);            // (12, 32)
    dim3 gMlp1(D4/64,  ROWS/128);            // (48, 32)
    dim3 gFA  (TT/64,  BB*HH);               // (16, 48)
    dim3 gLM  (ROWS/128, VV/64);             // (32, 500)

    for (int l = 0; l < LL; l++) {
        size_t wqkvl = (size_t)l * D3 * DD;
        size_t wl    = (size_t)l * DD * DD;
        size_t w1l   = (size_t)l * D4 * DD;
        size_t w2l   = (size_t)l * DD * D4;

        ln_planes<<<ROWS, 192>>>(x, h_hi, h_lo, ln1_g + l*DD, ln1_b + l*DD);

        gemm_bf16<<<gQKV, 256>>>(h_hi, h_lo, DD,
                                 wqkvT_hi + wqkvl, wqkvT_lo + wqkvl, DD,
                                 DD, 3, nullptr, 0,
                                 q_hi, q_lo, DD,
                                 k_hi, k_lo,
                                 nullptr, nullptr, 0);

        flash_attn<<<gFA, 128, FA_SMEM>>>(q_hi, q_lo, k_hi, k_lo, vT_hi, vT_lo, o_hi, o_lo);

        gemm_bf16<<<gProj, 256>>>(o_hi, o_lo, DD, woT_hi + wl, woT_lo + wl, DD,
                                  DD, 0, x, DD, nullptr, nullptr, 0,
                                  nullptr, nullptr,
                                  bo + l*DD, x, 0);

        ln_planes<<<ROWS, 192>>>(x, h_hi, h_lo, ln2_g + l*DD, ln2_b + l*DD);
        gemm_bf16<<<gMlp1, 256>>>(h_hi, h_lo, DD, w1T_hi + w1l, w1T_lo + w1l, DD,
                                  DD, 1, nullptr, 0, m_hi, m_lo, D4,
                                  nullptr, nullptr,
                                  b1 + (size_t)l*D4, nullptr, 1 /*relu*/);
        gemm_bf16<<<gProj, 256>>>(m_hi, m_lo, D4, w2T_hi + w2l, w2T_lo + w2l, D4,
                                  D4, 0, x, DD, nullptr, nullptr, 0,
                                  nullptr, nullptr,
                                  b2 + l*DD, x, 0);
    }

    ln_f16<<<ROWS, 192>>>(x, h16, lnf_g, lnf_b);
    gemm_lm<<<gLM, 256>>>(h16, wlm16, (float*)d_out, b_lm);
}

// round 17
// speedup vs baseline: 1.0293x; 1.0136x over previous
#include <cuda_runtime.h>
#include <cuda_bf16.h>
#include <cuda_fp16.h>
#include <math.h>
#include <stdint.h>

// Problem constants (MiniGPT: B=4, T=1024, D=768, H=12, L=4, V=32000, HD=64)
#define BB 4
#define TT 1024
#define DD 768
#define HH 12
#define LL 4
#define VV 32000
#define HD 64
#define D4 (4*DD)
#define D3 (3*DD)

// ---------------------------------------------------------------------------
// Scratch (device globals). bf16 "planes" are (hi, lo) split pairs.
// ---------------------------------------------------------------------------
__device__ float g_x[BB*TT*DD];

#define PLANE(name, n) \
  __device__ __align__(256) __nv_bfloat16 name##_hi[n]; \
  __device__ __align__(256) __nv_bfloat16 name##_lo[n];

PLANE(g_h,  BB*TT*DD)
PLANE(g_q,  BB*TT*DD)
PLANE(g_k,  BB*TT*DD)
PLANE(g_vT, BB*TT*DD)                 // [b][d][t] transposed V
PLANE(g_o,  BB*TT*DD)
PLANE(g_m,  (size_t)BB*TT*D4)         // MLP hidden
// transposed weights [N,K]; QKV concatenated: [L][3*DD][DD]
PLANE(g_wqkvT, (size_t)LL*D3*DD)
PLANE(g_woT, LL*DD*DD)
PLANE(g_w1T, (size_t)LL*D4*DD)
PLANE(g_w2T, (size_t)LL*DD*D4)
// LM head: single-plane fp16 path (error budget measured R8/R10: ~2e-4/side)
__device__ __align__(256) __half g_wlm16[(size_t)VV*DD];
__device__ __align__(256) __half g_h16[BB*TT*DD];

// ---------------------------------------------------------------------------
// Helpers
// ---------------------------------------------------------------------------
__device__ __forceinline__ void split1(float x, __nv_bfloat16 &h, __nv_bfloat16 &l) {
    h = __float2bfloat16_rn(x);
    l = __float2bfloat16_rn(x - __bfloat162float(h));
}
__device__ __forceinline__ void split2pack(float x, float y, uint32_t &hi, uint32_t &lo) {
    __nv_bfloat16 xh, xl, yh, yl;
    split1(x, xh, xl); split1(y, yh, yl);
    hi = (uint32_t)__bfloat16_as_ushort(xh) | ((uint32_t)__bfloat16_as_ushort(yh) << 16);
    lo = (uint32_t)__bfloat16_as_ushort(xl) | ((uint32_t)__bfloat16_as_ushort(yl) << 16);
}
__device__ __forceinline__ void ldsm4(uint32_t &r0, uint32_t &r1, uint32_t &r2, uint32_t &r3, uint32_t a) {
    asm volatile("ldmatrix.sync.aligned.m8n8.x4.shared.b16 {%0,%1,%2,%3}, [%4];\n"
                 : "=r"(r0), "=r"(r1), "=r"(r2), "=r"(r3) : "r"(a));
}
__device__ __forceinline__ void mma16816(float* d, const uint32_t* a, uint32_t b0, uint32_t b1) {
    asm volatile("mma.sync.aligned.m16n8k16.row.col.f32.bf16.bf16.f32 "
                 "{%0,%1,%2,%3},{%4,%5,%6,%7},{%8,%9},{%0,%1,%2,%3};\n"
                 : "+f"(d[0]), "+f"(d[1]), "+f"(d[2]), "+f"(d[3])
                 : "r"(a[0]), "r"(a[1]), "r"(a[2]), "r"(a[3]), "r"(b0), "r"(b1));
}
__device__ __forceinline__ void mma16816h(float* d, const uint32_t* a, uint32_t b0, uint32_t b1) {
    asm volatile("mma.sync.aligned.m16n8k16.row.col.f32.f16.f16.f32 "
                 "{%0,%1,%2,%3},{%4,%5,%6,%7},{%8,%9},{%0,%1,%2,%3};\n"
                 : "+f"(d[0]), "+f"(d[1]), "+f"(d[2]), "+f"(d[3])
                 : "r"(a[0]), "r"(a[1]), "r"(a[2]), "r"(a[3]), "r"(b0), "r"(b1));
}
__device__ __forceinline__ void cpa16(uint32_t dst, const void* src) {
    asm volatile("cp.async.cg.shared.global [%0], [%1], 16;\n" :: "r"(dst), "l"(src));
}
__device__ __forceinline__ void cp_commit() { asm volatile("cp.async.commit_group;\n"); }
template<int N> __device__ __forceinline__ void cp_waitg() {
    asm volatile("cp.async.wait_group %0;\n" :: "n"(N));
}
__device__ __forceinline__ void cp_wait1() { asm volatile("cp.async.wait_group 1;\n"); }
__device__ __forceinline__ void cp_wait0() { asm volatile("cp.async.wait_group 0;\n"); }
// byte offset of 16B chunk c (0..3) in a 64B row, XOR swizzle for ldmatrix
__device__ __forceinline__ uint32_t swzc(int row, int c) {
    return (uint32_t)(row * 64 + ((c ^ ((row >> 1) & 3)) << 4));
}

// ---------------------------------------------------------------------------
// Weight prep: transpose [K,N] fp32 -> [N,K] bf16 hi/lo planes.
// Packed uint32 stores: each output slot covers 2 adjacent K elements.
// ---------------------------------------------------------------------------
__global__ void transpose_split(const float* __restrict__ in,
                                __nv_bfloat16* __restrict__ oh,
                                __nv_bfloat16* __restrict__ ol,
                                int K, int N, long long ostride) {
    in += (size_t)blockIdx.z * K * N;
    oh += (size_t)blockIdx.z * ostride;
    ol += (size_t)blockIdx.z * ostride;
    __shared__ float tile[32][33];     // tile[k_local][n_local]
    int n0 = blockIdx.x * 32, k0 = blockIdx.y * 32;
    int tx = threadIdx.x, ty = threadIdx.y;
    int tid = ty * 32 + tx;            // 0..255
    #pragma unroll
    for (int i = 0; i < 4; i++)
        tile[ty + i*8][tx] = in[(size_t)(k0 + ty + i*8) * N + n0 + tx];
    __syncthreads();
    // 512 uint32 slots = 32 n-rows x 16 k-pairs; 2 slots per thread.
    #pragma unroll
    for (int j = 0; j < 2; j++) {
        int slot = tid + j * 256;
        int n  = slot >> 4;            // 0..31
        int k2 = slot & 15;            // 0..15 (pair of k)
        float v0 = tile[2*k2][n];
        float v1 = tile[2*k2 + 1][n];
        uint32_t hi, lo;
        split2pack(v0, v1, hi, lo);
        size_t off = (size_t)(n0 + n) * K + k0 + 2*k2;
        *(uint32_t*)(oh + off) = hi;
        *(uint32_t*)(ol + off) = lo;
    }
}

// fp16 single-plane variant (LM head weights), packed __half2 stores
__global__ void transpose_f16(const float* __restrict__ in,
                              __half* __restrict__ oh,
                              int K, int N) {
    __shared__ float tile[32][33];
    int n0 = blockIdx.x * 32, k0 = blockIdx.y * 32;
    int tx = threadIdx.x, ty = threadIdx.y;
    int tid = ty * 32 + tx;
    #pragma unroll
    for (int i = 0; i < 4; i++)
        tile[ty + i*8][tx] = in[(size_t)(k0 + ty + i*8) * N + n0 + tx];
    __syncthreads();
    #pragma unroll
    for (int j = 0; j < 2; j++) {
        int slot = tid + j * 256;
        int n  = slot >> 4;
        int k2 = slot & 15;
        __half2 p = __floats2half2_rn(tile[2*k2][n], tile[2*k2 + 1][n]);
        size_t off = (size_t)(n0 + n) * K + k0 + 2*k2;
        *(__half2*)(oh + off) = p;
    }
}

// ---------------------------------------------------------------------------
// Embedding (float4 vectorized)
// ---------------------------------------------------------------------------
__global__ void embed_kernel(const int* __restrict__ idx,
                             const float* __restrict__ tok,
                             const float* __restrict__ pos,
                             float* __restrict__ x) {
    int i = blockIdx.x * blockDim.x + threadIdx.x;     // element/4 index
    if (i >= BB*TT*DD/4) return;
    int d4 = i % (DD/4);
    int bt = i / (DD/4);
    int t  = bt % TT;
    float4 tv = ((const float4*)(tok + (size_t)idx[bt]*DD))[d4];
    float4 pv = ((const float4*)(pos + (size_t)t*DD))[d4];
    tv.x += pv.x; tv.y += pv.y; tv.z += pv.z; tv.w += pv.w;
    ((float4*)x)[i] = tv;
}

// ---------------------------------------------------------------------------
// LayerNorm fp32 -> bf16 hi/lo planes. 192 threads, one float4 per thread.
// ---------------------------------------------------------------------------
__global__ void ln_planes(const float* __restrict__ in,
                          __nv_bfloat16* __restrict__ oh,
                          __nv_bfloat16* __restrict__ ol,
                          const float* __restrict__ gw, const float* __restrict__ bw) {
    int row = blockIdx.x;
    const float4* x4 = (const float4*)(in + (size_t)row*DD);
    int tid = threadIdx.x;        // 0..191

    float4 v = x4[tid];
    float s  = v.x + v.y + v.z + v.w;
    float s2 = v.x*v.x + v.y*v.y + v.z*v.z + v.w*v.w;
    #pragma unroll
    for (int o = 16; o; o >>= 1) {
        s  += __shfl_xor_sync(0xffffffffu, s,  o);
        s2 += __shfl_xor_sync(0xffffffffu, s2, o);
    }
    __shared__ float r1[6], r2[6];
    __shared__ float smean, sinv;
    int w = tid >> 5;
    if ((tid & 31) == 0) { r1[w] = s; r2[w] = s2; }
    __syncthreads();
    if (tid == 0) {
        float a = 0.f, b2 = 0.f;
        #pragma unroll
        for (int i = 0; i < 6; i++) { a += r1[i]; b2 += r2[i]; }
        float mean = a / DD;
        float var  = b2 / DD - mean*mean;
        smean = mean;
        sinv  = rsqrtf(var + 1e-5f);
    }
    __syncthreads();
    float mean = smean, inv = sinv;
    float4 gv = ((const float4*)gw)[tid];
    float4 bv = ((const float4*)bw)[tid];
    float y0 = (v.x - mean) * inv * gv.x + bv.x;
    float y1 = (v.y - mean) * inv * gv.y + bv.y;
    float y2 = (v.z - mean) * inv * gv.z + bv.z;
    float y3 = (v.w - mean) * inv * gv.w + bv.w;
    size_t off = (size_t)row*DD + tid*4;
    uint32_t h0, l0, h1, l1;
    split2pack(y0, y1, h0, l0);
    split2pack(y2, y3, h1, l1);
    *(uint32_t*)(oh + off)     = h0;
    *(uint32_t*)(oh + off + 2) = h1;
    *(uint32_t*)(ol + off)     = l0;
    *(uint32_t*)(ol + off + 2) = l1;
}

// LayerNorm fp32 -> single fp16 plane (final LN, feeds LM head). 192 threads.
__global__ void ln_f16(const float* __restrict__ in,
                       __half* __restrict__ o16,
                       const float* __restrict__ gw, const float* __restrict__ bw) {
    int row = blockIdx.x;
    const float4* x4 = (const float4*)(in + (size_t)row*DD);
    int tid = threadIdx.x;

    float4 v = x4[tid];
    float s  = v.x + v.y + v.z + v.w;
    float s2 = v.x*v.x + v.y*v.y + v.z*v.z + v.w*v.w;
    #pragma unroll
    for (int o = 16; o; o >>= 1) {
        s  += __shfl_xor_sync(0xffffffffu, s,  o);
        s2 += __shfl_xor_sync(0xffffffffu, s2, o);
    }
    __shared__ float r1[6], r2[6];
    __shared__ float smean, sinv;
    int w = tid >> 5;
    if ((tid & 31) == 0) { r1[w] = s; r2[w] = s2; }
    __syncthreads();
    if (tid == 0) {
        float a = 0.f, b2 = 0.f;
        #pragma unroll
        for (int i = 0; i < 6; i++) { a += r1[i]; b2 += r2[i]; }
        float mean = a / DD;
        float var  = b2 / DD - mean*mean;
        smean = mean;
        sinv  = rsqrtf(var + 1e-5f);
    }
    __syncthreads();
    float mean = smean, inv = sinv;
    float4 gv = ((const float4*)gw)[tid];
    float4 bv = ((const float4*)bw)[tid];
    __half2 p0 = __floats2half2_rn((v.x - mean) * inv * gv.x + bv.x,
                                   (v.y - mean) * inv * gv.y + bv.y);
    __half2 p1 = __floats2half2_rn((v.z - mean) * inv * gv.z + bv.z,
                                   (v.w - mean) * inv * gv.w + bv.w);
    size_t off = (size_t)row*DD + tid*4;
    *(__half2*)(o16 + off)     = p0;
    *(__half2*)(o16 + off + 2) = p1;
}

// ---------------------------------------------------------------------------
// Flash attention (causal), split-bf16 3-term. 3-deep KV ring, ONE sync/iter.
// q is pre-scaled by 0.125 in the QKV epilogue.
// ---------------------------------------------------------------------------
#define FA_SMEM 114688
__global__ __launch_bounds__(128)
void flash_attn(const __nv_bfloat16* __restrict__ qh, const __nv_bfloat16* __restrict__ ql,
                const __nv_bfloat16* __restrict__ kh, const __nv_bfloat16* __restrict__ kl,
                const __nv_bfloat16* __restrict__ vh, const __nv_bfloat16* __restrict__ vl,
                __nv_bfloat16* __restrict__ oh, __nv_bfloat16* __restrict__ ol) {
    int bh = blockIdx.y;
    int b = bh / HH, h = bh % HH;
    int qt = (TT/64 - 1) - blockIdx.x;

    extern __shared__ __align__(16) uint8_t fsm[];
    uint32_t smQ = (uint32_t)__cvta_generic_to_shared(fsm);
    uint32_t smK = smQ + 16384;
    uint32_t smV = smQ + 65536;

    int tid = threadIdx.x;
    int lane = tid & 31, warp = tid >> 5;
    int lq = lane & 15, l4 = lane >> 4, g = lane >> 2, c2 = (lane & 3) * 2;

    const size_t bq = (size_t)b * TT;
    const int hc = h * 64;

    #pragma unroll
    for (int j = 0; j < 8; j++) {
        int id = tid + j * 128;
        int pl = id >> 9, rem = id & 511;
        int ck = rem >> 8, r = (rem >> 2) & 63, c = rem & 3;
        const __nv_bfloat16* src = (pl ? ql : qh) + (bq + qt*64 + r) * DD + hc + ck*32 + c*8;
        cpa16(smQ + pl*8192 + ck*4096 + swzc(r, c), src);
    }

    auto load_kv = [&](int kt) {
        uint32_t kb = smK + (kt % 3) * 16384;
        uint32_t vb = smV + (kt % 3) * 16384;
        #pragma unroll
        for (int j = 0; j < 16; j++) {
            int id = tid + j * 128;
            int isV = id >> 10;
            int q = id & 1023;
            int pl = q >> 9, rem = q & 511;
            int ck = rem >> 8, r = (rem >> 2) & 63, c = rem & 3;
            if (!isV) {
                const __nv_bfloat16* src = (pl ? kl : kh) + (bq + kt*64 + r) * DD + hc + ck*32 + c*8;
                cpa16(kb + pl*8192 + ck*4096 + swzc(r, c), src);
            } else {
                const __nv_bfloat16* src = (pl ? vl : vh) + ((size_t)b * DD + hc + r) * TT + kt*64 + ck*32 + c*8;
                cpa16(vb + pl*8192 + ck*4096 + swzc(r, c), src);
            }
        }
        cp_commit();
    };

    load_kv(0);

    float oacc[8][4];
    #pragma unroll
    for (int i = 0; i < 8; i++)
        #pragma unroll
        for (int e = 0; e < 4; e++) oacc[i][e] = 0.f;
    float mA = -1e30f, mB = -1e30f, lA = 0.f, lB = 0.f;

    for (int kt = 0; kt <= qt; kt++) {
        if (kt < qt) { load_kv(kt + 1); cp_wait1(); } else { cp_wait0(); }
        __syncthreads();
        uint32_t kb = smK + (kt % 3) * 16384;
        uint32_t vb = smV + (kt % 3) * 16384;

        float sacc[8][4];
        #pragma unroll
        for (int i = 0; i < 8; i++)
            #pragma unroll
            for (int e = 0; e < 4; e++) sacc[i][e] = 0.f;

        #pragma unroll
        for (int ks = 0; ks < 4; ks++) {
            int quarter = (ks & 1) * 2 + l4;
            int rQ = warp * 16 + lq;
            uint32_t offQ = (uint32_t)((ks >> 1) * 4096 + rQ * 64 + ((quarter ^ ((rQ >> 1) & 3)) << 4));
            uint32_t aqh[4], aql[4];
            ldsm4(aqh[0], aqh[1], aqh[2], aqh[3], smQ + offQ);
            ldsm4(aql[0], aql[1], aql[2], aql[3], smQ + 8192 + offQ);
            #pragma unroll
            for (int nb = 0; nb < 4; nb++) {
                int rK = nb * 16 + lq;
                uint32_t offK = (uint32_t)((ks >> 1) * 4096 + rK * 64 + ((quarter ^ ((rK >> 1) & 3)) << 4));
                uint32_t bh4[4], bl4[4];
                ldsm4(bh4[0], bh4[1], bh4[2], bh4[3], kb + offK);
                ldsm4(bl4[0], bl4[1], bl4[2], bl4[3], kb + 8192 + offK);
                mma16816(sacc[2*nb],   aqh, bh4[0], bh4[2]);
                mma16816(sacc[2*nb],   aqh, bl4[0], bl4[2]);
                mma16816(sacc[2*nb],   aql, bh4[0], bh4[2]);
                mma16816(sacc[2*nb+1], aqh, bh4[1], bh4[3]);
                mma16816(sacc[2*nb+1], aqh, bl4[1], bl4[3]);
                mma16816(sacc[2*nb+1], aql, bh4[1], bh4[3]);
            }
        }

        if (kt == qt) {
            int r0 = qt * 64 + warp * 16 + g;
            #pragma unroll
            for (int i = 0; i < 8; i++)
                #pragma unroll
                for (int e = 0; e < 4; e++) {
                    int t_g = kt * 64 + i * 8 + c2 + (e & 1);
                    int row = r0 + ((e >> 1) << 3);
                    if (t_g > row) sacc[i][e] = -1e30f;
                }
        }

        float nmA = -1e30f, nmB = -1e30f;
        #pragma unroll
        for (int i = 0; i < 8; i++) {
            nmA = fmaxf(nmA, fmaxf(sacc[i][0], sacc[i][1]));
            nmB = fmaxf(nmB, fmaxf(sacc[i][2], sacc[i][3]));
        }
        nmA = fmaxf(nmA, __shfl_xor_sync(0xffffffffu, nmA, 1));
        nmA = fmaxf(nmA, __shfl_xor_sync(0xffffffffu, nmA, 2));
        nmB = fmaxf(nmB, __shfl_xor_sync(0xffffffffu, nmB, 1));
        nmB = fmaxf(nmB, __shfl_xor_sync(0xffffffffu, nmB, 2));
        float mnA = fmaxf(mA, nmA), mnB = fmaxf(mB, nmB);
        float corrA = expf(mA - mnA), corrB = expf(mB - mnB);
        mA = mnA; mB = mnB;

        float sA = 0.f, sB = 0.f;
        #pragma unroll
        for (int i = 0; i < 8; i++) {
            float p0 = expf(sacc[i][0] - mnA);
            float p1 = expf(sacc[i][1] - mnA);
            float p2 = expf(sacc[i][2] - mnB);
            float p3 = expf(sacc[i][3] - mnB);
            sacc[i][0] = p0; sacc[i][1] = p1; sacc[i][2] = p2; sacc[i][3] = p3;
            sA += p0 + p1; sB += p2 + p3;
        }
        sA += __shfl_xor_sync(0xffffffffu, sA, 1);
        sA += __shfl_xor_sync(0xffffffffu, sA, 2);
        sB += __shfl_xor_sync(0xffffffffu, sB, 1);
        sB += __shfl_xor_sync(0xffffffffu, sB, 2);
        lA = lA * corrA + sA;
        lB = lB * corrB + sB;
        #pragma unroll
        for (int i = 0; i < 8; i++) {
            oacc[i][0] *= corrA; oacc[i][1] *= corrA;
            oacc[i][2] *= corrB; oacc[i][3] *= corrB;
        }

        #pragma unroll
        for (int j2 = 0; j2 < 4; j2++) {
            uint32_t pah[4], pal[4];
            split2pack(sacc[2*j2][0],   sacc[2*j2][1],   pah[0], pal[0]);
            split2pack(sacc[2*j2][2],   sacc[2*j2][3],   pah[1], pal[1]);
            split2pack(sacc[2*j2+1][0], sacc[2*j2+1][1], pah[2], pal[2]);
            split2pack(sacc[2*j2+1][2], sacc[2*j2+1][3], pah[3], pal[3]);
            int quarter = (j2 & 1) * 2 + l4;
            #pragma unroll
            for (int nb = 0; nb < 4; nb++) {
                int rV = nb * 16 + lq;
                uint32_t off = (uint32_t)((j2 >> 1) * 4096 + rV * 64 + ((quarter ^ ((rV >> 1) & 3)) << 4));
                uint32_t vh4[4], vl4[4];
                ldsm4(vh4[0], vh4[1], vh4[2], vh4[3], vb + off);
                ldsm4(vl4[0], vl4[1], vl4[2], vl4[3], vb + 8192 + off);
                mma16816(oacc[2*nb],   pah, vh4[0], vh4[2]);
                mma16816(oacc[2*nb],   pah, vl4[0], vl4[2]);
                mma16816(oacc[2*nb],   pal, vh4[0], vh4[2]);
                mma16816(oacc[2*nb+1], pah, vh4[1], vh4[3]);
                mma16816(oacc[2*nb+1], pah, vl4[1], vl4[3]);
                mma16816(oacc[2*nb+1], pal, vh4[1], vh4[3]);
            }
        }
    }

    float rA = 1.f / lA, rB = 1.f / lB;
    size_t row0 = bq + (size_t)qt * 64 + warp * 16 + g;
    #pragma unroll
    for (int i = 0; i < 8; i++) {
        int col = hc + i * 8 + c2;
        uint32_t hi, lo;
        split2pack(oacc[i][0] * rA, oacc[i][1] * rA, hi, lo);
        *(uint32_t*)(oh + row0 * DD + col) = hi;
        *(uint32_t*)(ol + row0 * DD + col) = lo;
        split2pack(oacc[i][2] * rB, oacc[i][3] * rB, hi, lo);
        *(uint32_t*)(oh + (row0 + 8) * DD + col) = hi;
        *(uint32_t*)(ol + (row0 + 8) * DD + col) = lo;
    }
}

// ---------------------------------------------------------------------------
// Dense split-bf16 GEMM: C = act(A@B^T + bias [+resid])
//   Block tile 128x64xK32; 8 warps (4x2); 3-stage cp.async ring, 1 sync/tile.
//   mode 0: fp32 out; mode 1: planes out; mode 2: vT planes out;
//   mode 3: QKV routing by N-segment (seg0->q planes *0.125, seg1->k, seg2->vT).
// ---------------------------------------------------------------------------
__global__ __launch_bounds__(256, 3)
void gemm_bf16(const __nv_bfloat16* __restrict__ Ah, const __nv_bfloat16* __restrict__ Al,
               int lda,
               const __nv_bfloat16* __restrict__ Bh, const __nv_bfloat16* __restrict__ Bl,
               int ldb,
               int K, int mode,
               float* __restrict__ C, int ldc,
               __nv_bfloat16* __restrict__ Ch, __nv_bfloat16* __restrict__ Cl, int ldcp,
               __nv_bfloat16* __restrict__ Kh, __nv_bfloat16* __restrict__ Kl,
               const float* __restrict__ bias, const float* __restrict__ resid,
               int relu) {
    int bm = blockIdx.y * 128;
    int bn = blockIdx.x * 64;

    __shared__ __align__(16) uint8_t smbuf[3 * 24576];
    uint32_t smbase = (uint32_t)__cvta_generic_to_shared(smbuf);

    int tid = threadIdx.x;
    int lane = tid & 31, warp = tid >> 5;
    int wm = warp & 3, wn = warp >> 2;

    int nk = K / 32;

    auto issue = [&](int kb) {
        int k0 = kb * 32;
        uint32_t base = smbase + (kb % 3) * 24576;
        #pragma unroll
        for (int j = 0; j < 4; j++) {
            int lin = tid + j * 256;
            int pl = lin >> 9, rc = lin & 511, r = rc >> 2, c = rc & 3;
            const __nv_bfloat16* src = (pl ? Al : Ah) + (long long)(bm + r) * lda + k0 + c * 8;
            cpa16(base + pl * 8192 + swzc(r, c), src);
        }
        #pragma unroll
        for (int j = 0; j < 2; j++) {
            int lin = tid + j * 256;
            int pl = lin >> 8, rc = lin & 255, r = rc >> 2, c = rc & 3;
            const __nv_bfloat16* src = (pl ? Bl : Bh) + (long long)(bn + r) * ldb + k0 + c * 8;
            cpa16(base + 16384 + pl * 4096 + swzc(r, c), src);
        }
        cp_commit();
    };

    float acc[2][4][4];
    #pragma unroll
    for (int i = 0; i < 2; i++)
        #pragma unroll
        for (int j = 0; j < 4; j++)
            #pragma unroll
            for (int e = 0; e < 4; e++) acc[i][j][e] = 0.f;

    issue(0);
    if (nk > 1) issue(1);

    for (int kb = 0; kb < nk; kb++) {
        if (kb + 1 < nk) cp_waitg<1>(); else cp_waitg<0>();
        __syncthreads();
        if (kb + 2 < nk) issue(kb + 2);
        uint32_t base = smbase + (kb % 3) * 24576;

        #pragma unroll
        for (int ks = 0; ks < 2; ks++) {
            uint32_t ah[2][4], al[2][4], bh[2][4], bl[2][4];
            int chunk = ks * 2 + (lane >> 4);
            int rowA0 = wm * 32 + (lane & 15);
            #pragma unroll
            for (int mm = 0; mm < 2; mm++) {
                int r = rowA0 + mm * 16;
                uint32_t off = (uint32_t)(r * 64 + ((chunk ^ ((r >> 1) & 3)) << 4));
                ldsm4(ah[mm][0], ah[mm][1], ah[mm][2], ah[mm][3], base + off);
                ldsm4(al[mm][0], al[mm][1], al[mm][2], al[mm][3], base + 8192 + off);
            }
            int rowB0 = wn * 32 + (lane & 15);
            #pragma unroll
            for (int nb = 0; nb < 2; nb++) {
                int r = rowB0 + nb * 16;
                uint32_t off = (uint32_t)(r * 64 + ((chunk ^ ((r >> 1) & 3)) << 4));
                ldsm4(bh[nb][0], bh[nb][1], bh[nb][2], bh[nb][3], base + 16384 + off);
                ldsm4(bl[nb][0], bl[nb][1], bl[nb][2], bl[nb][3], base + 20480 + off);
            }
            #pragma unroll
            for (int mm = 0; mm < 2; mm++) {
                #pragma unroll
                for (int nf = 0; nf < 4; nf++) {
                    uint32_t b0h = bh[nf >> 1][nf & 1], b1h = bh[nf >> 1][(nf & 1) + 2];
                    uint32_t b0l = bl[nf >> 1][nf & 1], b1l = bl[nf >> 1][(nf & 1) + 2];
                    mma16816(acc[mm][nf], ah[mm], b0h, b1h);
                    mma16816(acc[mm][nf], ah[mm], b0l, b1l);
                    mma16816(acc[mm][nf], al[mm], b0h, b1h);
                }
            }
        }
    }

    // ---- epilogue (mode-3 routing resolved first) ----
    int bnc = bn;
    __nv_bfloat16 *Oh = Ch, *Ol = Cl;
    int emode = mode;
    float escale = 1.f;
    if (mode == 3) {
        int seg = bn / DD;
        bnc = bn - seg * DD;
        if (seg == 0)      { Oh = Ch; Ol = Cl; emode = 1; escale = 0.125f; }
        else if (seg == 1) { Oh = Kh; Ol = Kl; emode = 1; }
        else               { emode = 2; }
    }

    int ml = lane >> 2, nl = (lane & 3) * 2;
    #pragma unroll
    for (int mm = 0; mm < 2; mm++) {
        #pragma unroll
        for (int nf = 0; nf < 4; nf++) {
            int col = bnc + wn * 32 + nf * 8 + nl;
            float bx = 0.f, by = 0.f;
            if (bias) { float2 bb = *(const float2*)(bias + col); bx = bb.x; by = bb.y; }
            int r0 = bm + wm * 32 + mm * 16 + ml;
            #pragma unroll
            for (int hh = 0; hh < 2; hh++) {
                int r = r0 + hh * 8;
                float vx = acc[mm][nf][hh * 2 + 0] + bx;
                float vy = acc[mm][nf][hh * 2 + 1] + by;
                if (emode == 0) {
                    long long off = (long long)r * ldc + col;
                    if (resid) {
                        float2 rr = *(const float2*)(resid + off);
                        vx += rr.x; vy += rr.y;
                    }
                    if (relu) { vx = fmaxf(vx, 0.f); vy = fmaxf(vy, 0.f); }
                    float2 v; v.x = vx; v.y = vy;
                    *(float2*)(C + off) = v;
                } else if (emode == 1) {
                    if (relu) { vx = fmaxf(vx, 0.f); vy = fmaxf(vy, 0.f); }
                    vx *= escale; vy *= escale;
                    long long off = (long long)r * ldcp + col;
                    uint32_t hi, lo;
                    split2pack(vx, vy, hi, lo);
                    *(uint32_t*)(Oh + off) = hi;
                    *(uint32_t*)(Ol + off) = lo;
                } else { // emode 2: vT[b][col][t], r = b*TT + t
                    int b = r >> 10, t = r & 1023;
                    long long off = ((long long)b * DD + col) * TT + t;
                    __nv_bfloat16 h0, l0, h1, l1;
                    split1(vx, h0, l0);
                    split1(vy, h1, l1);
                    __nv_bfloat16* th = (mode == 2) ? Ch : g_vT_hi;
                    __nv_bfloat16* tl = (mode == 2) ? Cl : g_vT_lo;
                    th[off] = h0;       tl[off] = l0;
                    th[off + TT] = h1;  tl[off + TT] = l1;
                }
            }
        }
    }
}

// ---------------------------------------------------------------------------
// LM head GEMM: logits = h16 @ wlm16^T + bias, single fp16 plane each side.
//   Grid (M-tiles=32 fastest, N-tiles=500) for B reuse in L2.
//   Block tile 128x64xK32; 8 warps (4x2); 3-stage cp.async ring (36KB smem).
// ---------------------------------------------------------------------------
__global__ __launch_bounds__(256, 3)
void gemm_lm(const __half* __restrict__ Ah,
             const __half* __restrict__ Bh,
             float* __restrict__ C, const float* __restrict__ bias) {
    int bm = blockIdx.x * 128;    // M fastest-varying
    int bn = blockIdx.y * 64;

    __shared__ __align__(16) uint8_t smbuf[3 * 12288];  // A 8K | B 4K per stage
    uint32_t smbase = (uint32_t)__cvta_generic_to_shared(smbuf);

    int tid = threadIdx.x;
    int lane = tid & 31, warp = tid >> 5;
    int wm = warp & 3, wn = warp >> 2;

    const int nk = DD / 32;   // 24

    auto issue = [&](int kb) {
        int k0 = kb * 32;
        uint32_t base = smbase + (kb % 3) * 12288;
        #pragma unroll
        for (int j = 0; j < 2; j++) {           // A: 128 rows x 4 chunks = 512
            int lin = tid + j * 256;
            int r = lin >> 2, c = lin & 3;
            cpa16(base + swzc(r, c), Ah + (long long)(bm + r) * DD + k0 + c * 8);
        }
        {                                        // B: 64 rows x 4 chunks = 256
            int r = tid >> 2, c = tid & 3;
            cpa16(base + 8192 + swzc(r, c), Bh + (long long)(bn + r) * DD + k0 + c * 8);
        }
        cp_commit();
    };

    float acc[2][4][4];
    #pragma unroll
    for (int i = 0; i < 2; i++)
        #pragma unroll
        for (int j = 0; j < 4; j++)
            #pragma unroll
            for (int e = 0; e < 4; e++) acc[i][j][e] = 0.f;

    issue(0);
    issue(1);

    for (int kb = 0; kb < nk; kb++) {
        if (kb + 1 < nk) cp_waitg<1>(); else cp_waitg<0>();
        __syncthreads();
        if (kb + 2 < nk) issue(kb + 2);
        uint32_t base = smbase + (kb % 3) * 12288;

        #pragma unroll
        for (int ks = 0; ks < 2; ks++) {
            uint32_t ah[2][4], bh[2][4];
            int chunk = ks * 2 + (lane >> 4);
            int rowA0 = wm * 32 + (lane & 15);
            #pragma unroll
            for (int mm = 0; mm < 2; mm++) {
                int r = rowA0 + mm * 16;
                uint32_t off = (uint32_t)(r * 64 + ((chunk ^ ((r >> 1) & 3)) << 4));
                ldsm4(ah[mm][0], ah[mm][1], ah[mm][2], ah[mm][3], base + off);
            }
            int rowB0 = wn * 32 + (lane & 15);
            #pragma unroll
            for (int nb = 0; nb < 2; nb++) {
                int r = rowB0 + nb * 16;
                uint32_t off = (uint32_t)(r * 64 + ((chunk ^ ((r >> 1) & 3)) << 4));
                ldsm4(bh[nb][0], bh[nb][1], bh[nb][2], bh[nb][3], base + 8192 + off);
            }
            #pragma unroll
            for (int mm = 0; mm < 2; mm++) {
                #pragma unroll
                for (int nf = 0; nf < 4; nf++) {
                    uint32_t b0h = bh[nf >> 1][nf & 1], b1h = bh[nf >> 1][(nf & 1) + 2];
                    mma16816h(acc[mm][nf], ah[mm], b0h, b1h);
                }
            }
        }
    }

    int ml = lane >> 2, nl = (lane & 3) * 2;
    #pragma unroll
    for (int mm = 0; mm < 2; mm++) {
        #pragma unroll
        for (int nf = 0; nf < 4; nf++) {
            int col = bn + wn * 32 + nf * 8 + nl;
            float2 bb = *(const float2*)(bias + col);
            int r0 = bm + wm * 32 + mm * 16 + ml;
            #pragma unroll
            for (int hh = 0; hh < 2; hh++) {
                int r = r0 + hh * 8;
                float2 v;
                v.x = acc[mm][nf][hh * 2 + 0] + bb.x;
                v.y = acc[mm][nf][hh * 2 + 1] + bb.y;
                *(float2*)(C + (long long)r * VV + col) = v;
            }
        }
    }
}

// ---------------------------------------------------------------------------
// Host orchestration. Weight prep runs on a forked side stream so it overlaps
// layer-0 compute; event fork/join keeps the graph capture valid.
// Stream/events are created once, on the (uncaptured) correctness call.
// ---------------------------------------------------------------------------
#define GETSYM(p, sym) cudaGetSymbolAddress((void**)&p, sym)

extern "C" void kernel_launch(void* const* d_in, const int* in_sizes, int n_in,
                              void* d_out, int out_size) {
    const int*   idx    = (const int*)  d_in[0];
    const float* tok    = (const float*)d_in[1];
    const float* pos    = (const float*)d_in[2];
    const float* wq     = (const float*)d_in[3];
    const float* wk     = (const float*)d_in[4];
    const float* wv     = (const float*)d_in[5];
    const float* wo     = (const float*)d_in[6];
    const float* bo     = (const float*)d_in[7];
    const float* ln1_g  = (const float*)d_in[8];
    const float* ln1_b  = (const float*)d_in[9];
    const float* ln2_g  = (const float*)d_in[10];
    const float* ln2_b  = (const float*)d_in[11];
    const float* w1     = (const float*)d_in[12];
    const float* b1     = (const float*)d_in[13];
    const float* w2     = (const float*)d_in[14];
    const float* b2     = (const float*)d_in[15];
    const float* lnf_g  = (const float*)d_in[16];
    const float* lnf_b  = (const float*)d_in[17];
    const float* w_lm   = (const float*)d_in[18];
    const float* b_lm   = (const float*)d_in[19];

    float *x;
    GETSYM(x, g_x);
    __nv_bfloat16 *h_hi,*h_lo,*q_hi,*q_lo,*k_hi,*k_lo,*vT_hi,*vT_lo,*o_hi,*o_lo,
                  *m_hi,*m_lo,
                  *wqkvT_hi,*wqkvT_lo,*woT_hi,*woT_lo,
                  *w1T_hi,*w1T_lo,*w2T_hi,*w2T_lo;
    __half *wlm16, *h16;
    GETSYM(h_hi, g_h_hi);   GETSYM(h_lo, g_h_lo);
    GETSYM(q_hi, g_q_hi);   GETSYM(q_lo, g_q_lo);
    GETSYM(k_hi, g_k_hi);   GETSYM(k_lo, g_k_lo);
    GETSYM(vT_hi, g_vT_hi); GETSYM(vT_lo, g_vT_lo);
    GETSYM(o_hi, g_o_hi);   GETSYM(o_lo, g_o_lo);
    GETSYM(m_hi, g_m_hi);   GETSYM(m_lo, g_m_lo);
    GETSYM(wqkvT_hi, g_wqkvT_hi); GETSYM(wqkvT_lo, g_wqkvT_lo);
    GETSYM(woT_hi, g_woT_hi); GETSYM(woT_lo, g_woT_lo);
    GETSYM(w1T_hi, g_w1T_hi); GETSYM(w1T_lo, g_w1T_lo);
    GETSYM(w2T_hi, g_w2T_hi); GETSYM(w2T_lo, g_w2T_lo);
    GETSYM(wlm16, g_wlm16);
    GETSYM(h16, g_h16);

    cudaFuncSetAttribute(flash_attn, cudaFuncAttributeMaxDynamicSharedMemorySize, FA_SMEM);

    // One-time stream/event creation (correctness call is not captured).
    static cudaStream_t s2 = nullptr;
    static cudaEvent_t evFork, evQKV, evWO, evW1, evW2, evLM;
    if (s2 == nullptr) {
        cudaStreamCreateWithFlags(&s2, cudaStreamNonBlocking);
        cudaEventCreateWithFlags(&evFork, cudaEventDisableTiming);
        cudaEventCreateWithFlags(&evQKV,  cudaEventDisableTiming);
        cudaEventCreateWithFlags(&evWO,   cudaEventDisableTiming);
        cudaEventCreateWithFlags(&evW1,   cudaEventDisableTiming);
        cudaEventCreateWithFlags(&evW2,   cudaEventDisableTiming);
        cudaEventCreateWithFlags(&evLM,   cudaEventDisableTiming);
    }

    const int ROWS = BB * TT;
    dim3 tb(32, 8);
    const long long QKV_OS = (long long)D3 * DD;

    // ---- fork: weight prep on side stream ----
    cudaEventRecord(evFork, 0);
    cudaStreamWaitEvent(s2, evFork, 0);

    transpose_split<<<dim3(DD/32, DD/32, LL), tb, 0, s2>>>(wq, wqkvT_hi,           wqkvT_lo,           DD, DD, QKV_OS);
    transpose_split<<<dim3(DD/32, DD/32, LL), tb, 0, s2>>>(wk, wqkvT_hi + DD*DD,   wqkvT_lo + DD*DD,   DD, DD, QKV_OS);
    transpose_split<<<dim3(DD/32, DD/32, LL), tb, 0, s2>>>(wv, wqkvT_hi + 2*DD*DD, wqkvT_lo + 2*DD*DD, DD, DD, QKV_OS);
    cudaEventRecord(evQKV, s2);
    transpose_split<<<dim3(DD/32, DD/32, LL), tb, 0, s2>>>(wo, woT_hi, woT_lo, DD, DD, (long long)DD*DD);
    cudaEventRecord(evWO, s2);
    transpose_split<<<dim3(D4/32, DD/32, LL), tb, 0, s2>>>(w1, w1T_hi, w1T_lo, DD, D4, (long long)D4*DD);
    cudaEventRecord(evW1, s2);
    transpose_split<<<dim3(DD/32, D4/32, LL), tb, 0, s2>>>(w2, w2T_hi, w2T_lo, D4, DD, (long long)DD*D4);
    cudaEventRecord(evW2, s2);
    transpose_f16<<<dim3(VV/32, DD/32, 1), tb, 0, s2>>>(w_lm, wlm16, DD, VV);
    cudaEventRecord(evLM, s2);

    // ---- main chain on default stream ----
    embed_kernel<<<(BB*TT*DD/4 + 255)/256, 256>>>(idx, tok, pos, x);

    dim3 gQKV (D3/64,  ROWS/128);            // (36, 32)
    dim3 gProj(DD/64,  ROWS/128);            // (12, 32)
    dim3 gMlp1(D4/64,  ROWS/128);            // (48, 32)
    dim3 gFA  (TT/64,  BB*HH);               // (16, 48)
    dim3 gLM  (ROWS/128, VV/64);             // (32, 500)

    for (int l = 0; l < LL; l++) {
        size_t wqkvl = (size_t)l * D3 * DD;
        size_t wl    = (size_t)l * DD * DD;
        size_t w1l   = (size_t)l * D4 * DD;
        size_t w2l   = (size_t)l * DD * D4;

        ln_planes<<<ROWS, 192>>>(x, h_hi, h_lo, ln1_g + l*DD, ln1_b + l*DD);

        if (l == 0) cudaStreamWaitEvent(0, evQKV, 0);
        gemm_bf16<<<gQKV, 256>>>(h_hi, h_lo, DD,
                                 wqkvT_hi + wqkvl, wqkvT_lo + wqkvl, DD,
                                 DD, 3, nullptr, 0,
                                 q_hi, q_lo, DD,
                                 k_hi, k_lo,
                                 nullptr, nullptr, 0);

        flash_attn<<<gFA, 128, FA_SMEM>>>(q_hi, q_lo, k_hi, k_lo, vT_hi, vT_lo, o_hi, o_lo);

        if (l == 0) cudaStreamWaitEvent(0, evWO, 0);
        gemm_bf16<<<gProj, 256>>>(o_hi, o_lo, DD, woT_hi + wl, woT_lo + wl, DD,
                                  DD, 0, x, DD, nullptr, nullptr, 0,
                                  nullptr, nullptr,
                                  bo + l*DD, x, 0);

        ln_planes<<<ROWS, 192>>>(x, h_hi, h_lo, ln2_g + l*DD, ln2_b + l*DD);
        if (l == 0) cudaStreamWaitEvent(0, evW1, 0);
        gemm_bf16<<<gMlp1, 256>>>(h_hi, h_lo, DD, w1T_hi + w1l, w1T_lo + w1l, DD,
                                  DD, 1, nullptr, 0, m_hi, m_lo, D4,
                                  nullptr, nullptr,
                                  b1 + (size_t)l*D4, nullptr, 1 /*relu*/);
        if (l == 0) cudaStreamWaitEvent(0, evW2, 0);
        gemm_bf16<<<gProj, 256>>>(m_hi, m_lo, D4, w2T_hi + w2l, w2T_lo + w2l, D4,
                                  D4, 0, x, DD, nullptr, nullptr, 0,
                                  nullptr, nullptr,
                                  b2 + l*DD, x, 0);
    }

    ln_f16<<<ROWS, 192>>>(x, h16, lnf_g, lnf_b);
    cudaStreamWaitEvent(0, evLM, 0);   // join: all side-stream work merges here
    gemm_lm<<<gLM, 256>>>(h16, wlm16, (float*)d_out, b_lm);
}